// round 3
// baseline (speedup 1.0000x reference)
#include <cuda_runtime.h>
#include <cstdint>
#include <math.h>

#define BB 16
#define NN 32768
#define DD 256
#define EE 512
#define HH 8
#define KK 512
#define TT 16

// ---------------- device scratch (no allocations allowed) ----------------
__device__ float g_gath[BB * KK * DD];       // gathered feats   8 MB
__device__ float g_x[BB * KK * EE];          // projected x     16 MB
__device__ float g_kv[BB * KK * 2 * EE];     // k|v concat      32 MB
__device__ float g_q[BB * TT * EE];          // q (16 rows)
__device__ float g_o[BB * TT * EE];          // attn out
__device__ int   g_idx[BB * KK];             // top-k indices

// order-preserving float->uint key (bigger key == bigger float)
__device__ __forceinline__ unsigned fkey(float f) {
    unsigned u = __float_as_uint(f);
    return (u & 0x80000000u) ? ~u : (u | 0x80000000u);
}

// ---------------- top-K via MSB radix select + bitonic sort ----------------
__global__ void __launch_bounds__(512) topk_kernel(const float* __restrict__ scores) {
    const int b = blockIdx.x;
    const float* s = scores + (size_t)b * NN;
    const int tid = threadIdx.x;  // 512 threads

    __shared__ unsigned hist[256];
    __shared__ unsigned sh_prefix, sh_mask, sh_remk;
    __shared__ int sh_cntgt, sh_cnteq;
    __shared__ unsigned long long sel[512];
    __shared__ int eq[1024];

    if (tid == 0) { sh_prefix = 0u; sh_mask = 0u; sh_remk = KK; }
    __syncthreads();

    for (int pass = 0; pass < 4; pass++) {
        const int shift = 24 - pass * 8;
        if (tid < 256) hist[tid] = 0u;
        __syncthreads();
        const unsigned prefix = sh_prefix, mask = sh_mask;
        for (int i = tid; i < NN; i += 512) {
            unsigned k = fkey(__ldg(&s[i]));
            if ((k & mask) == prefix) atomicAdd(&hist[(k >> shift) & 255u], 1u);
        }
        __syncthreads();
        if (tid == 0) {
            unsigned remk = sh_remk, acc = 0u;
            int d;
            for (d = 255; d >= 0; d--) {
                if (acc + hist[d] >= remk) break;
                acc += hist[d];
            }
            sh_remk  = remk - acc;
            sh_prefix = prefix | ((unsigned)d << shift);
            sh_mask   = mask | (0xFFu << shift);
            sh_cntgt = 0; sh_cnteq = 0;
        }
        __syncthreads();
    }

    const unsigned Tkey = sh_prefix;
    const int remk = (int)sh_remk;

    // gather: strictly-greater always in; equals collected for index tie-break
    for (int i = tid; i < NN; i += 512) {
        unsigned k = fkey(__ldg(&s[i]));
        if (k > Tkey) {
            int p = atomicAdd(&sh_cntgt, 1);
            sel[p] = ((unsigned long long)k << 32) | (unsigned)(0xFFFFFFFFu - (unsigned)i);
        } else if (k == Tkey) {
            int p = atomicAdd(&sh_cnteq, 1);
            if (p < 1024) eq[p] = i;
        }
    }
    __syncthreads();
    const int cntgt = sh_cntgt;
    const int cnteq = min(sh_cnteq, 1024);

    // sort equal-key indices ascending (ties -> lower index first)
    for (int i = tid; i < 1024; i += 512)
        if (i >= cnteq) eq[i] = 0x7FFFFFFF;
    __syncthreads();
    for (unsigned k = 2; k <= 1024; k <<= 1)
        for (unsigned j = k >> 1; j > 0; j >>= 1) {
            __syncthreads();
            for (unsigned i = tid; i < 1024; i += 512) {
                unsigned ixj = i ^ j;
                if (ixj > i) {
                    int a = eq[i], c = eq[ixj];
                    bool up = ((i & k) == 0);
                    if ((a > c) == up) { eq[i] = c; eq[ixj] = a; }
                }
            }
        }
    __syncthreads();
    for (int jj = tid; jj < remk; jj += 512)
        sel[cntgt + jj] = ((unsigned long long)Tkey << 32) |
                          (unsigned)(0xFFFFFFFFu - (unsigned)eq[jj]);
    __syncthreads();

    // bitonic ascending sort of 512 packed (key, ~idx); read reversed = jax order
    for (unsigned k = 2; k <= 512; k <<= 1)
        for (unsigned j = k >> 1; j > 0; j >>= 1) {
            __syncthreads();
            unsigned i = tid, ixj = i ^ j;
            if (ixj > i) {
                unsigned long long a = sel[i], c = sel[ixj];
                bool up = ((i & k) == 0);
                if ((a > c) == up) { sel[i] = c; sel[ixj] = a; }
            }
        }
    __syncthreads();
    g_idx[b * KK + tid] =
        (int)(0xFFFFFFFFu - (unsigned)(sel[511 - tid] & 0xFFFFFFFFull));
}

// ---------------- gather selected rows ----------------
__global__ void __launch_bounds__(64) gather_kernel(const float* __restrict__ feats) {
    const int t = blockIdx.x, b = blockIdx.y;
    const int src = g_idx[b * KK + t];
    const float4* sp = (const float4*)(feats + ((size_t)b * NN + src) * DD);
    float4* dp = (float4*)(g_gath + ((size_t)b * KK + t) * DD);
    dp[threadIdx.x] = sp[threadIdx.x];   // 64 threads * float4 = 256 floats
}

// ---------------- generic batched NT GEMM: C = A @ W^T + bias ----------------
// A: [M x Kd] per batch (stride strideA), W: [N x Kd] shared, C: [M x N] (stride strideC)
__global__ void __launch_bounds__(256, 2)
gemm_nt_bias(const float* __restrict__ A, long long strideA,
             const float* __restrict__ W,
             const float* __restrict__ bias,
             float* __restrict__ C, long long strideC,
             int M, int N, int Kd) {
    const int b = blockIdx.z;
    A += (long long)b * strideA;
    C += (long long)b * strideC;

    __shared__ float As[16][64];
    __shared__ float Bs[16][64];

    const int tid = threadIdx.x;          // 256
    const int tx = tid & 15, ty = tid >> 4;
    const int row0 = blockIdx.y * 64, col0 = blockIdx.x * 64;
    const int ar = tid >> 2, ac = (tid & 3) << 2;

    float acc[4][4];
#pragma unroll
    for (int i = 0; i < 4; i++)
#pragma unroll
        for (int j = 0; j < 4; j++) acc[i][j] = 0.f;

    for (int k0 = 0; k0 < Kd; k0 += 16) {
        float4 av = make_float4(0.f, 0.f, 0.f, 0.f);
        float4 bv = make_float4(0.f, 0.f, 0.f, 0.f);
        if (row0 + ar < M) av = *(const float4*)(A + (long long)(row0 + ar) * Kd + k0 + ac);
        if (col0 + ar < N) bv = *(const float4*)(W + (long long)(col0 + ar) * Kd + k0 + ac);
        __syncthreads();
        As[ac + 0][ar] = av.x; As[ac + 1][ar] = av.y;
        As[ac + 2][ar] = av.z; As[ac + 3][ar] = av.w;
        Bs[ac + 0][ar] = bv.x; Bs[ac + 1][ar] = bv.y;
        Bs[ac + 2][ar] = bv.z; Bs[ac + 3][ar] = bv.w;
        __syncthreads();
#pragma unroll
        for (int k = 0; k < 16; k++) {
            float a[4], bb[4];
            *(float4*)a  = *(const float4*)&As[k][ty << 2];
            *(float4*)bb = *(const float4*)&Bs[k][tx << 2];
#pragma unroll
            for (int i = 0; i < 4; i++)
#pragma unroll
                for (int j = 0; j < 4; j++)
                    acc[i][j] = fmaf(a[i], bb[j], acc[i][j]);
        }
    }
#pragma unroll
    for (int i = 0; i < 4; i++) {
        int m = row0 + (ty << 2) + i;
        if (m < M) {
#pragma unroll
            for (int j = 0; j < 4; j++) {
                int n = col0 + (tx << 2) + j;
                C[(long long)m * N + n] = acc[i][j] + bias[n];
            }
        }
    }
}

// ---------------- attention for 16 queries, per (head, batch) ----------------
__global__ void __launch_bounds__(256) attn_kernel() {
    const int h = blockIdx.x, b = blockIdx.y;
    const float* qb = g_q + ((size_t)b * TT) * EE + h * 64;
    const float* kb = g_kv + (size_t)b * KK * 2 * EE + h * 64;
    const float* vb = kb + EE;

    __shared__ float qs[TT][64];
    __shared__ float lg[TT][KK];
    const int tid = threadIdx.x;  // 256

    for (int i = tid; i < TT * 64; i += 256) {
        int t = i >> 6, d = i & 63;
        qs[t][d] = qb[t * EE + d] * 0.125f;   // 1/sqrt(64)
    }
    __syncthreads();

    // logits
    for (int kk = tid; kk < KK; kk += 256) {
        const float4* krow = (const float4*)(kb + (size_t)kk * (2 * EE));
        float acc[TT];
#pragma unroll
        for (int t = 0; t < TT; t++) acc[t] = 0.f;
#pragma unroll
        for (int d4 = 0; d4 < 16; d4++) {
            float4 k4 = krow[d4];
#pragma unroll
            for (int t = 0; t < TT; t++) {
                acc[t] += qs[t][d4 * 4 + 0] * k4.x + qs[t][d4 * 4 + 1] * k4.y +
                          qs[t][d4 * 4 + 2] * k4.z + qs[t][d4 * 4 + 3] * k4.w;
            }
        }
#pragma unroll
        for (int t = 0; t < TT; t++) lg[t][kk] = acc[t];
    }
    __syncthreads();

    // softmax: each of 8 warps owns 2 rows
    const int w = tid >> 5, lane = tid & 31;
    for (int t = w; t < TT; t += 8) {
        float m = -1e30f;
        for (int i = lane; i < KK; i += 32) m = fmaxf(m, lg[t][i]);
#pragma unroll
        for (int o = 16; o > 0; o >>= 1) m = fmaxf(m, __shfl_xor_sync(0xFFFFFFFFu, m, o));
        float ssum = 0.f;
        for (int i = lane; i < KK; i += 32) {
            float e = __expf(lg[t][i] - m);
            lg[t][i] = e; ssum += e;
        }
#pragma unroll
        for (int o = 16; o > 0; o >>= 1) ssum += __shfl_xor_sync(0xFFFFFFFFu, ssum, o);
        float inv = 1.f / ssum;
        for (int i = lane; i < KK; i += 32) lg[t][i] *= inv;
    }
    __syncthreads();

    // o = attn @ v
    const int d = tid & 63;
    for (int t = tid >> 6; t < TT; t += 4) {
        float acc = 0.f;
        for (int kk = 0; kk < KK; kk++)
            acc = fmaf(lg[t][kk], vb[(size_t)kk * 2 * EE + d], acc);
        g_o[((size_t)b * TT + t) * EE + h * 64 + d] = acc;
    }
}

// ---------------- out_proj + residual + LN + FFN(GELU) + residual ----------------
__global__ void __launch_bounds__(256)
epilogue_kernel(const float* __restrict__ Wo, const float* __restrict__ bo,
                const float* __restrict__ lng, const float* __restrict__ lnb,
                const float* __restrict__ Wf, const float* __restrict__ bf,
                float* __restrict__ out) {
    const int t = blockIdx.x, b = blockIdx.y;
    const int tid = threadIdx.x;  // 256
    __shared__ float orow[EE], zrow[EE];
    __shared__ float red[256];

    const float* op = g_o + ((size_t)b * TT + t) * EE;
    const float* xp = g_x + ((size_t)b * KK + t) * EE;
    for (int e = tid; e < EE; e += 256) orow[e] = op[e];
    __syncthreads();

    float y[2];
#pragma unroll
    for (int u = 0; u < 2; u++) {
        int e = tid + u * 256;
        const float4* wr = (const float4*)(Wo + (size_t)e * EE);
        float acc = bo[e];
#pragma unroll 4
        for (int f4 = 0; f4 < EE / 4; f4++) {
            float4 wv = wr[f4];
            acc += orow[f4 * 4 + 0] * wv.x + orow[f4 * 4 + 1] * wv.y +
                   orow[f4 * 4 + 2] * wv.z + orow[f4 * 4 + 3] * wv.w;
        }
        y[u] = xp[e] + acc;
    }

    // layernorm (two-pass, matches reference)
    red[tid] = y[0] + y[1];
    __syncthreads();
    for (int o = 128; o > 0; o >>= 1) {
        if (tid < o) red[tid] += red[tid + o];
        __syncthreads();
    }
    const float mu = red[0] / EE;
    __syncthreads();
    float d0 = y[0] - mu, d1 = y[1] - mu;
    red[tid] = d0 * d0 + d1 * d1;
    __syncthreads();
    for (int o = 128; o > 0; o >>= 1) {
        if (tid < o) red[tid] += red[tid + o];
        __syncthreads();
    }
    const float rstd = rsqrtf(red[0] / EE + 1e-5f);

#pragma unroll
    for (int u = 0; u < 2; u++) {
        int e = tid + u * 256;
        zrow[e] = (y[u] - mu) * rstd * lng[e] + lnb[e];
    }
    __syncthreads();

    float* outp = out + ((size_t)b * TT + t) * EE;
#pragma unroll
    for (int u = 0; u < 2; u++) {
        int e = tid + u * 256;
        const float4* wr = (const float4*)(Wf + (size_t)e * EE);
        float acc = bf[e];
#pragma unroll 4
        for (int f4 = 0; f4 < EE / 4; f4++) {
            float4 wv = wr[f4];
            acc += zrow[f4 * 4 + 0] * wv.x + zrow[f4 * 4 + 1] * wv.y +
                   zrow[f4 * 4 + 2] * wv.z + zrow[f4 * 4 + 3] * wv.w;
        }
        float gelu = 0.5f * acc * (1.f + erff(acc * 0.70710678118654752f));
        outp[e] = zrow[e] + gelu;
    }
}

// ---------------- launch ----------------
extern "C" void kernel_launch(void* const* d_in, const int* in_sizes, int n_in,
                              void* d_out, int out_size) {
    (void)in_sizes; (void)n_in; (void)out_size;
    const float* feats  = (const float*)d_in[0];
    const float* scores = (const float*)d_in[1];
    const float* proj_w = (const float*)d_in[2];
    const float* proj_b = (const float*)d_in[3];
    const float* in_w   = (const float*)d_in[4];
    const float* in_b   = (const float*)d_in[5];
    const float* out_w  = (const float*)d_in[6];
    const float* out_b  = (const float*)d_in[7];
    const float* ln_g   = (const float*)d_in[8];
    const float* ln_b   = (const float*)d_in[9];
    const float* ffn_w  = (const float*)d_in[10];
    const float* ffn_b  = (const float*)d_in[11];
    float* out = (float*)d_out;

    float *pgath, *px, *pkv, *pq;
    cudaGetSymbolAddress((void**)&pgath, g_gath);
    cudaGetSymbolAddress((void**)&px,    g_x);
    cudaGetSymbolAddress((void**)&pkv,   g_kv);
    cudaGetSymbolAddress((void**)&pq,    g_q);

    topk_kernel<<<BB, 512>>>(scores);
    gather_kernel<<<dim3(KK, BB), 64>>>(feats);
    // x = gathered @ proj_w^T + proj_b            [512 x 512] per batch
    gemm_nt_bias<<<dim3(EE / 64, KK / 64, BB), 256>>>(
        pgath, (long long)KK * DD, proj_w, proj_b, px, (long long)KK * EE,
        KK, EE, DD);
    // kv = x @ [Wk;Wv]^T + b                      [512 x 1024] per batch
    gemm_nt_bias<<<dim3(2 * EE / 64, KK / 64, BB), 256>>>(
        px, (long long)KK * EE, in_w + EE * EE, in_b + EE, pkv,
        (long long)KK * 2 * EE, KK, 2 * EE, EE);
    // q = x[:16] @ Wq^T + bq                      [16 x 512] per batch
    gemm_nt_bias<<<dim3(EE / 64, 1, BB), 256>>>(
        px, (long long)KK * EE, in_w, in_b, pq, (long long)TT * EE,
        TT, EE, EE);
    attn_kernel<<<dim3(HH, BB), 256>>>();
    epilogue_kernel<<<dim3(TT, BB), 256>>>(out_w, out_b, ln_g, ln_b, ffn_w, ffn_b, out);
}

// round 4
// speedup vs baseline: 1.3238x; 1.3238x over previous
#include <cuda_runtime.h>
#include <cstdint>
#include <math.h>

#define BB 16
#define NN 32768
#define DD 256
#define EE 512
#define HH 8
#define KK 512
#define TT 16

// ---------------- device scratch (no allocations allowed) ----------------
__device__ float g_gath[BB * KK * DD];       // gathered feats   8 MB
__device__ float g_x[BB * KK * EE];          // projected x     16 MB
__device__ float g_kv[BB * KK * 2 * EE];     // k|v concat      32 MB
__device__ float g_q[BB * TT * EE];          // q (16 rows)
__device__ float g_o[BB * TT * EE];          // attn out (256 x 512)
__device__ float g_y[BB * TT * EE];          // post out_proj + residual
__device__ float g_z[BB * TT * EE];          // post layernorm
__device__ int   g_idx[BB * KK];             // top-k indices

// order-preserving float->uint key (bigger key == bigger float)
__device__ __forceinline__ unsigned fkey(float f) {
    unsigned u = __float_as_uint(f);
    return (u & 0x80000000u) ? ~u : (u | 0x80000000u);
}

// ---------------- top-K via MSB radix select + bitonic sort ----------------
__global__ void __launch_bounds__(512) topk_kernel(const float* __restrict__ scores) {
    const int b = blockIdx.x;
    const float* s = scores + (size_t)b * NN;
    const int tid = threadIdx.x;  // 512 threads

    __shared__ unsigned hist[256];
    __shared__ unsigned sh_prefix, sh_mask, sh_remk;
    __shared__ int sh_cntgt, sh_cnteq;
    __shared__ unsigned long long sel[512];
    __shared__ int eq[1024];

    if (tid == 0) { sh_prefix = 0u; sh_mask = 0u; sh_remk = KK; }
    __syncthreads();

    for (int pass = 0; pass < 4; pass++) {
        const int shift = 24 - pass * 8;
        if (tid < 256) hist[tid] = 0u;
        __syncthreads();
        const unsigned prefix = sh_prefix, mask = sh_mask;
        for (int i = tid; i < NN; i += 512) {
            unsigned k = fkey(__ldg(&s[i]));
            if ((k & mask) == prefix) atomicAdd(&hist[(k >> shift) & 255u], 1u);
        }
        __syncthreads();
        if (tid == 0) {
            unsigned remk = sh_remk, acc = 0u;
            int d;
            for (d = 255; d >= 0; d--) {
                if (acc + hist[d] >= remk) break;
                acc += hist[d];
            }
            sh_remk  = remk - acc;
            sh_prefix = prefix | ((unsigned)d << shift);
            sh_mask   = mask | (0xFFu << shift);
            sh_cntgt = 0; sh_cnteq = 0;
        }
        __syncthreads();
    }

    const unsigned Tkey = sh_prefix;
    const int remk = (int)sh_remk;

    // gather: strictly-greater always in; equals collected for index tie-break
    for (int i = tid; i < NN; i += 512) {
        unsigned k = fkey(__ldg(&s[i]));
        if (k > Tkey) {
            int p = atomicAdd(&sh_cntgt, 1);
            sel[p] = ((unsigned long long)k << 32) | (unsigned)(0xFFFFFFFFu - (unsigned)i);
        } else if (k == Tkey) {
            int p = atomicAdd(&sh_cnteq, 1);
            if (p < 1024) eq[p] = i;
        }
    }
    __syncthreads();
    const int cntgt = sh_cntgt;
    const int cnteq = min(sh_cnteq, 1024);

    // sort equal-key indices ascending (ties -> lower index first)
    for (int i = tid; i < 1024; i += 512)
        if (i >= cnteq) eq[i] = 0x7FFFFFFF;
    __syncthreads();
    for (unsigned k = 2; k <= 1024; k <<= 1)
        for (unsigned j = k >> 1; j > 0; j >>= 1) {
            __syncthreads();
            for (unsigned i = tid; i < 1024; i += 512) {
                unsigned ixj = i ^ j;
                if (ixj > i) {
                    int a = eq[i], c = eq[ixj];
                    bool up = ((i & k) == 0);
                    if ((a > c) == up) { eq[i] = c; eq[ixj] = a; }
                }
            }
        }
    __syncthreads();
    for (int jj = tid; jj < remk; jj += 512)
        sel[cntgt + jj] = ((unsigned long long)Tkey << 32) |
                          (unsigned)(0xFFFFFFFFu - (unsigned)eq[jj]);
    __syncthreads();

    // bitonic ascending sort of 512 packed (key, ~idx); read reversed = jax order
    for (unsigned k = 2; k <= 512; k <<= 1)
        for (unsigned j = k >> 1; j > 0; j >>= 1) {
            __syncthreads();
            unsigned i = tid, ixj = i ^ j;
            if (ixj > i) {
                unsigned long long a = sel[i], c = sel[ixj];
                bool up = ((i & k) == 0);
                if ((a > c) == up) { sel[i] = c; sel[ixj] = a; }
            }
        }
    __syncthreads();
    g_idx[b * KK + tid] =
        (int)(0xFFFFFFFFu - (unsigned)(sel[511 - tid] & 0xFFFFFFFFull));
}

// ---------------- gather selected rows ----------------
__global__ void __launch_bounds__(64) gather_kernel(const float* __restrict__ feats) {
    const int t = blockIdx.x, b = blockIdx.y;
    const int src = g_idx[b * KK + t];
    const float4* sp = (const float4*)(feats + ((size_t)b * NN + src) * DD);
    float4* dp = (float4*)(g_gath + ((size_t)b * KK + t) * DD);
    dp[threadIdx.x] = sp[threadIdx.x];   // 64 threads * float4 = 256 floats
}

// ====================== big-tile GEMM: C = A @ W^T + bias =================
// 128x128 tile, 8x8 per thread, double-buffered smem. M,N multiples of 128
// implied by grid (gridDim.y*128 rows, gridDim.x*128 cols). Kd % 16 == 0.
#define LDP 132   // padded smem leading dim (conflict-free transposed stores)

#define G128_STS(BUF)                                                     \
    {                                                                     \
        float* as = As[BUF]; float* bs = Bs[BUF];                         \
        as[(lc + 0) * LDP + lr]      = ag0.x;                             \
        as[(lc + 1) * LDP + lr]      = ag0.y;                             \
        as[(lc + 2) * LDP + lr]      = ag0.z;                             \
        as[(lc + 3) * LDP + lr]      = ag0.w;                             \
        as[(lc + 0) * LDP + lr + 64] = ag1.x;                             \
        as[(lc + 1) * LDP + lr + 64] = ag1.y;                             \
        as[(lc + 2) * LDP + lr + 64] = ag1.z;                             \
        as[(lc + 3) * LDP + lr + 64] = ag1.w;                             \
        bs[(lc + 0) * LDP + lr]      = bg0.x;                             \
        bs[(lc + 1) * LDP + lr]      = bg0.y;                             \
        bs[(lc + 2) * LDP + lr]      = bg0.z;                             \
        bs[(lc + 3) * LDP + lr]      = bg0.w;                             \
        bs[(lc + 0) * LDP + lr + 64] = bg1.x;                             \
        bs[(lc + 1) * LDP + lr + 64] = bg1.y;                             \
        bs[(lc + 2) * LDP + lr + 64] = bg1.z;                             \
        bs[(lc + 3) * LDP + lr + 64] = bg1.w;                             \
    }

#define G128_COMPUTE(BUF)                                                 \
    _Pragma("unroll")                                                     \
    for (int k = 0; k < 16; k++) {                                        \
        float a[8], bb[8];                                                \
        *(float4*)&a[0]  = *(const float4*)&As[BUF][k * LDP + ty4];       \
        *(float4*)&a[4]  = *(const float4*)&As[BUF][k * LDP + 64 + ty4];  \
        *(float4*)&bb[0] = *(const float4*)&Bs[BUF][k * LDP + tx4];       \
        *(float4*)&bb[4] = *(const float4*)&Bs[BUF][k * LDP + 64 + tx4];  \
        _Pragma("unroll")                                                 \
        for (int i = 0; i < 8; i++)                                       \
            _Pragma("unroll")                                             \
            for (int j = 0; j < 8; j++)                                   \
                acc[i][j] = fmaf(a[i], bb[j], acc[i][j]);                 \
    }

__global__ void __launch_bounds__(256)
gemm128(const float* __restrict__ A, long long strideA,
        const float* __restrict__ W,
        const float* __restrict__ bias,
        float* __restrict__ C, long long strideC,
        int Kd) {
    const int b = blockIdx.z;
    const float* Ab = A + (long long)b * strideA;
    float* Cb = C + (long long)b * strideC;
    const int N = gridDim.x * 128;

    __shared__ float As[2][16 * LDP];
    __shared__ float Bs[2][16 * LDP];

    const int tid = threadIdx.x;
    const int tx4 = (tid & 15) * 4, ty4 = (tid >> 4) * 4;
    const int row0 = blockIdx.y * 128, col0 = blockIdx.x * 128;
    const int lr = tid >> 2;             // 0..63
    const int lc = (tid & 3) << 2;       // 0,4,8,12

    const float* Ar0 = Ab + (long long)(row0 + lr) * Kd + lc;
    const float* Ar1 = Ab + (long long)(row0 + lr + 64) * Kd + lc;
    const float* Wr0 = W + (long long)(col0 + lr) * Kd + lc;
    const float* Wr1 = W + (long long)(col0 + lr + 64) * Kd + lc;

    float acc[8][8];
#pragma unroll
    for (int i = 0; i < 8; i++)
#pragma unroll
        for (int j = 0; j < 8; j++) acc[i][j] = 0.f;

    float4 ag0 = *(const float4*)(Ar0);
    float4 ag1 = *(const float4*)(Ar1);
    float4 bg0 = *(const float4*)(Wr0);
    float4 bg1 = *(const float4*)(Wr1);
    G128_STS(0)
    __syncthreads();

    int buf = 0;
    for (int k0 = 16; k0 < Kd; k0 += 16) {
        ag0 = *(const float4*)(Ar0 + k0);
        ag1 = *(const float4*)(Ar1 + k0);
        bg0 = *(const float4*)(Wr0 + k0);
        bg1 = *(const float4*)(Wr1 + k0);
        G128_COMPUTE(buf)
        G128_STS(buf ^ 1)
        __syncthreads();
        buf ^= 1;
    }
    G128_COMPUTE(buf)

    // epilogue: bias + store (two float4 per row)
#pragma unroll
    for (int i = 0; i < 8; i++) {
        int m = row0 + ty4 + (i & 3) + ((i >= 4) ? 64 : 0);
        float4 v0, v1;
        v0.x = acc[i][0] + bias[col0 + tx4 + 0];
        v0.y = acc[i][1] + bias[col0 + tx4 + 1];
        v0.z = acc[i][2] + bias[col0 + tx4 + 2];
        v0.w = acc[i][3] + bias[col0 + tx4 + 3];
        v1.x = acc[i][4] + bias[col0 + 64 + tx4 + 0];
        v1.y = acc[i][5] + bias[col0 + 64 + tx4 + 1];
        v1.z = acc[i][6] + bias[col0 + 64 + tx4 + 2];
        v1.w = acc[i][7] + bias[col0 + 64 + tx4 + 3];
        *(float4*)(Cb + (long long)m * N + col0 + tx4)      = v0;
        *(float4*)(Cb + (long long)m * N + col0 + 64 + tx4) = v1;
    }
}

// ---------------- small NT GEMM (64x64 tile) with residual/activation -------
// resmode: 0=none, 1=res[m*N+n], 2=res[((m>>4)*KK + (m&15))*EE + n]
// act: 0=none, 1=exact GELU applied to (acc+bias) before residual add
__global__ void __launch_bounds__(256)
gemm_nt_bias(const float* __restrict__ A, long long strideA,
             const float* __restrict__ W,
             const float* __restrict__ bias,
             const float* __restrict__ res, int resmode, int act,
             float* __restrict__ C, long long strideC,
             int M, int N, int Kd) {
    const int b = blockIdx.z;
    A += (long long)b * strideA;
    C += (long long)b * strideC;

    __shared__ float As[16][64];
    __shared__ float Bs[16][64];

    const int tid = threadIdx.x;          // 256
    const int tx = tid & 15, ty = tid >> 4;
    const int row0 = blockIdx.y * 64, col0 = blockIdx.x * 64;
    const int ar = tid >> 2, ac = (tid & 3) << 2;

    float acc[4][4];
#pragma unroll
    for (int i = 0; i < 4; i++)
#pragma unroll
        for (int j = 0; j < 4; j++) acc[i][j] = 0.f;

    for (int k0 = 0; k0 < Kd; k0 += 16) {
        float4 av = make_float4(0.f, 0.f, 0.f, 0.f);
        float4 bv = make_float4(0.f, 0.f, 0.f, 0.f);
        if (row0 + ar < M) av = *(const float4*)(A + (long long)(row0 + ar) * Kd + k0 + ac);
        if (col0 + ar < N) bv = *(const float4*)(W + (long long)(col0 + ar) * Kd + k0 + ac);
        __syncthreads();
        As[ac + 0][ar] = av.x; As[ac + 1][ar] = av.y;
        As[ac + 2][ar] = av.z; As[ac + 3][ar] = av.w;
        Bs[ac + 0][ar] = bv.x; Bs[ac + 1][ar] = bv.y;
        Bs[ac + 2][ar] = bv.z; Bs[ac + 3][ar] = bv.w;
        __syncthreads();
#pragma unroll
        for (int k = 0; k < 16; k++) {
            float a[4], bb[4];
            *(float4*)a  = *(const float4*)&As[k][ty << 2];
            *(float4*)bb = *(const float4*)&Bs[k][tx << 2];
#pragma unroll
            for (int i = 0; i < 4; i++)
#pragma unroll
                for (int j = 0; j < 4; j++)
                    acc[i][j] = fmaf(a[i], bb[j], acc[i][j]);
        }
    }
#pragma unroll
    for (int i = 0; i < 4; i++) {
        int m = row0 + (ty << 2) + i;
        if (m < M) {
#pragma unroll
            for (int j = 0; j < 4; j++) {
                int n = col0 + (tx << 2) + j;
                float t = acc[i][j] + bias[n];
                if (act) t = 0.5f * t * (1.f + erff(t * 0.70710678118654752f));
                if (resmode == 1)      t += res[(long long)m * N + n];
                else if (resmode == 2) t += res[((long long)(m >> 4) * KK + (m & 15)) * EE + n];
                C[(long long)m * N + n] = t;
            }
        }
    }
}

// ---------------- attention for 16 queries, per (head, batch) ----------------
__global__ void __launch_bounds__(256) attn_kernel() {
    const int h = blockIdx.x, b = blockIdx.y;
    const float* qb = g_q + ((size_t)b * TT) * EE + h * 64;
    const float* kb = g_kv + (size_t)b * KK * 2 * EE + h * 64;
    const float* vb = kb + EE;

    __shared__ float qs[TT][64];
    __shared__ float lg[TT][KK];
    __shared__ float vs[32][68];
    const int tid = threadIdx.x;  // 256

    for (int i = tid; i < TT * 64; i += 256) {
        int t = i >> 6, d = i & 63;
        qs[t][d] = qb[t * EE + d] * 0.125f;   // 1/sqrt(64)
    }
    __syncthreads();

    // logits
    for (int kk = tid; kk < KK; kk += 256) {
        const float4* krow = (const float4*)(kb + (size_t)kk * (2 * EE));
        float acc[TT];
#pragma unroll
        for (int t = 0; t < TT; t++) acc[t] = 0.f;
#pragma unroll
        for (int d4 = 0; d4 < 16; d4++) {
            float4 k4 = krow[d4];
#pragma unroll
            for (int t = 0; t < TT; t++) {
                acc[t] += qs[t][d4 * 4 + 0] * k4.x + qs[t][d4 * 4 + 1] * k4.y +
                          qs[t][d4 * 4 + 2] * k4.z + qs[t][d4 * 4 + 3] * k4.w;
            }
        }
#pragma unroll
        for (int t = 0; t < TT; t++) lg[t][kk] = acc[t];
    }
    __syncthreads();

    // softmax: each of 8 warps owns 2 rows
    const int w = tid >> 5, lane = tid & 31;
    for (int t = w; t < TT; t += 8) {
        float m = -1e30f;
        for (int i = lane; i < KK; i += 32) m = fmaxf(m, lg[t][i]);
#pragma unroll
        for (int o = 16; o > 0; o >>= 1) m = fmaxf(m, __shfl_xor_sync(0xFFFFFFFFu, m, o));
        float ssum = 0.f;
        for (int i = lane; i < KK; i += 32) {
            float e = __expf(lg[t][i] - m);
            lg[t][i] = e; ssum += e;
        }
#pragma unroll
        for (int o = 16; o > 0; o >>= 1) ssum += __shfl_xor_sync(0xFFFFFFFFu, ssum, o);
        float inv = 1.f / ssum;
        for (int i = lane; i < KK; i += 32) lg[t][i] *= inv;
    }

    // o = attn @ v  via 32-row V tiles in smem
    const int d = tid & 63, tg = tid >> 6;           // tg in 0..3
    const int vr = tid >> 4;                          // 0..15
    const int vc = (tid & 15) * 4;
    float acc4[4] = {0.f, 0.f, 0.f, 0.f};
    for (int kk0 = 0; kk0 < KK; kk0 += 32) {
        __syncthreads();
        const float* vrow = vb + (size_t)(kk0 + vr) * (2 * EE) + vc;
        float4 v0 = *(const float4*)(vrow);
        float4 v1 = *(const float4*)(vrow + (size_t)16 * 2 * EE);
        *(float4*)&vs[vr][vc]      = v0;
        *(float4*)&vs[vr + 16][vc] = v1;
        __syncthreads();
#pragma unroll
        for (int r = 0; r < 32; r++) {
            float v = vs[r][d];
#pragma unroll
            for (int i = 0; i < 4; i++)
                acc4[i] = fmaf(lg[tg + i * 4][kk0 + r], v, acc4[i]);
        }
    }
#pragma unroll
    for (int i = 0; i < 4; i++)
        g_o[((size_t)b * TT + tg + i * 4) * EE + h * 64 + d] = acc4[i];
}

// ---------------- layernorm over rows of g_y -> g_z ----------------
__global__ void __launch_bounds__(128) ln_kernel(const float* __restrict__ lng,
                                                 const float* __restrict__ lnb) {
    const int row = blockIdx.x;   // 256 rows
    const int tid = threadIdx.x;  // 128
    const float* yr = g_y + (size_t)row * EE;
    float* zr = g_z + (size_t)row * EE;
    __shared__ float red[4];

    float v[4];
#pragma unroll
    for (int u = 0; u < 4; u++) v[u] = yr[tid + u * 128];

    float s = v[0] + v[1] + v[2] + v[3];
#pragma unroll
    for (int o = 16; o > 0; o >>= 1) s += __shfl_xor_sync(0xFFFFFFFFu, s, o);
    if ((tid & 31) == 0) red[tid >> 5] = s;
    __syncthreads();
    const float mu = (red[0] + red[1] + red[2] + red[3]) / EE;
    __syncthreads();

    float q = 0.f;
#pragma unroll
    for (int u = 0; u < 4; u++) { float dlt = v[u] - mu; q += dlt * dlt; }
#pragma unroll
    for (int o = 16; o > 0; o >>= 1) q += __shfl_xor_sync(0xFFFFFFFFu, q, o);
    if ((tid & 31) == 0) red[tid >> 5] = q;
    __syncthreads();
    const float rstd = rsqrtf((red[0] + red[1] + red[2] + red[3]) / EE + 1e-5f);

#pragma unroll
    for (int u = 0; u < 4; u++) {
        int e = tid + u * 128;
        zr[e] = (v[u] - mu) * rstd * lng[e] + lnb[e];
    }
}

// ---------------- launch ----------------
extern "C" void kernel_launch(void* const* d_in, const int* in_sizes, int n_in,
                              void* d_out, int out_size) {
    (void)in_sizes; (void)n_in; (void)out_size;
    const float* feats  = (const float*)d_in[0];
    const float* scores = (const float*)d_in[1];
    const float* proj_w = (const float*)d_in[2];
    const float* proj_b = (const float*)d_in[3];
    const float* in_w   = (const float*)d_in[4];
    const float* in_b   = (const float*)d_in[5];
    const float* out_w  = (const float*)d_in[6];
    const float* out_b  = (const float*)d_in[7];
    const float* ln_g   = (const float*)d_in[8];
    const float* ln_b   = (const float*)d_in[9];
    const float* ffn_w  = (const float*)d_in[10];
    const float* ffn_b  = (const float*)d_in[11];
    float* out = (float*)d_out;

    float *pgath, *px, *pkv, *pq, *po, *py, *pz;
    cudaGetSymbolAddress((void**)&pgath, g_gath);
    cudaGetSymbolAddress((void**)&px,    g_x);
    cudaGetSymbolAddress((void**)&pkv,   g_kv);
    cudaGetSymbolAddress((void**)&pq,    g_q);
    cudaGetSymbolAddress((void**)&po,    g_o);
    cudaGetSymbolAddress((void**)&py,    g_y);
    cudaGetSymbolAddress((void**)&pz,    g_z);

    topk_kernel<<<BB, 512>>>(scores);
    gather_kernel<<<dim3(KK, BB), 64>>>(feats);

    // x = gathered @ proj_w^T + proj_b            [512 x 512] per batch
    gemm128<<<dim3(EE / 128, KK / 128, BB), 256>>>(
        pgath, (long long)KK * DD, proj_w, proj_b, px, (long long)KK * EE, DD);
    // kv = x @ [Wk;Wv]^T + b                      [512 x 1024] per batch
    gemm128<<<dim3(2 * EE / 128, KK / 128, BB), 256>>>(
        px, (long long)KK * EE, in_w + EE * EE, in_b + EE, pkv,
        (long long)KK * 2 * EE, EE);
    // q = x[:16] @ Wq^T + bq                      [16 x 512] per batch
    gemm_nt_bias<<<dim3(EE / 64, 1, BB), 256>>>(
        px, (long long)KK * EE, in_w, in_b, nullptr, 0, 0, pq,
        (long long)TT * EE, TT, EE, EE);

    attn_kernel<<<dim3(HH, BB), 256>>>();

    // y = x[:, :16] + o @ Wo^T + bo               [256 x 512] flat over batches
    gemm_nt_bias<<<dim3(EE / 64, (BB * TT) / 64, 1), 256>>>(
        po, 0LL, out_w, out_b, px, 2, 0, py, 0LL, BB * TT, EE, EE);
    // z = layernorm(y)
    ln_kernel<<<BB * TT, 128>>>(ln_g, ln_b);
    // out = z + gelu(z @ Wf^T + bf)
    gemm_nt_bias<<<dim3(EE / 64, (BB * TT) / 64, 1), 256>>>(
        pz, 0LL, ffn_w, ffn_b, pz, 1, 1, out, 0LL, BB * TT, EE, EE);
}

// round 5
// speedup vs baseline: 1.4139x; 1.0680x over previous
#include <cuda_runtime.h>
#include <cstdint>
#include <math.h>

#define BB 16
#define NN 32768
#define DD 256
#define EE 512
#define HH 8
#define KK 512
#define TT 16

// ---------------- device scratch (no allocations allowed) ----------------
__device__ float g_x[BB * KK * EE];          // projected x     16 MB
__device__ float g_kv[BB * KK * 2 * EE];     // k|v concat      32 MB
__device__ float g_q[BB * TT * EE];          // q (256 x 512 flat)
__device__ float g_o[BB * TT * EE];          // attn out (256 x 512)
__device__ float g_y[BB * TT * EE];          // post out_proj + residual
__device__ float g_z[BB * TT * EE];          // post layernorm
__device__ int   g_idx[BB * KK];             // top-k indices

// order-preserving float->uint key (bigger key == bigger float)
__device__ __forceinline__ unsigned fkey(float f) {
    unsigned u = __float_as_uint(f);
    return (u & 0x80000000u) ? ~u : (u | 0x80000000u);
}

// ---------------- top-K: smem-resident keys, radix select + bitonic sort ----
extern __shared__ unsigned skeys[];   // NN unsigned = 128 KB dynamic smem

__global__ void __launch_bounds__(1024) topk_kernel(const float* __restrict__ scores) {
    const int b = blockIdx.x;
    const float* s = scores + (size_t)b * NN;
    const int tid = threadIdx.x;  // 1024 threads

    __shared__ unsigned hist[256];
    __shared__ unsigned sh_prefix, sh_mask, sh_remk;
    __shared__ int sh_cntgt, sh_cnteq;
    __shared__ unsigned long long sel[512];
    __shared__ int eq[1024];

    if (tid == 0) { sh_prefix = 0u; sh_mask = 0u; sh_remk = KK; }
    if (tid < 256) hist[tid] = 0u;
    __syncthreads();

    // load + first-pass histogram (prefix empty, counts all)
    for (int i = tid; i < NN; i += 1024) {
        unsigned k = fkey(__ldg(&s[i]));
        skeys[i] = k;
        atomicAdd(&hist[k >> 24], 1u);
    }
    __syncthreads();

    for (int pass = 0; pass < 4; pass++) {
        const int shift = 24 - pass * 8;
        if (tid == 0) {
            unsigned remk = sh_remk, acc = 0u;
            int d;
            for (d = 255; d >= 0; d--) {
                if (acc + hist[d] >= remk) break;
                acc += hist[d];
            }
            sh_remk  = remk - acc;
            sh_prefix = sh_prefix | ((unsigned)d << shift);
            sh_mask   = sh_mask | (0xFFu << shift);
            sh_cntgt = 0; sh_cnteq = 0;
        }
        __syncthreads();
        if (pass == 3) break;
        // next-pass histogram over smem keys
        if (tid < 256) hist[tid] = 0u;
        __syncthreads();
        const unsigned prefix = sh_prefix, mask = sh_mask;
        const int nshift = shift - 8;
        for (int i = tid; i < NN; i += 1024) {
            unsigned k = skeys[i];
            if ((k & mask) == prefix) atomicAdd(&hist[(k >> nshift) & 255u], 1u);
        }
        __syncthreads();
    }

    const unsigned Tkey = sh_prefix;
    const int remk = (int)sh_remk;

    // gather: strictly-greater always in; equals collected for index tie-break
    for (int i = tid; i < NN; i += 1024) {
        unsigned k = skeys[i];
        if (k > Tkey) {
            int p = atomicAdd(&sh_cntgt, 1);
            sel[p] = ((unsigned long long)k << 32) | (unsigned)(0xFFFFFFFFu - (unsigned)i);
        } else if (k == Tkey) {
            int p = atomicAdd(&sh_cnteq, 1);
            if (p < 1024) eq[p] = i;
        }
    }
    __syncthreads();
    const int cntgt = sh_cntgt;
    const int cnteq = min(sh_cnteq, 1024);

    // sort equal-key indices ascending (ties -> lower index first)
    if (tid >= cnteq) eq[tid] = 0x7FFFFFFF;
    __syncthreads();
    for (unsigned k = 2; k <= 1024; k <<= 1)
        for (unsigned j = k >> 1; j > 0; j >>= 1) {
            unsigned i = tid, ixj = i ^ j;
            if (ixj > i) {
                int a = eq[i], c = eq[ixj];
                bool up = ((i & k) == 0);
                if ((a > c) == up) { eq[i] = c; eq[ixj] = a; }
            }
            __syncthreads();
        }
    for (int jj = tid; jj < remk; jj += 1024)
        sel[cntgt + jj] = ((unsigned long long)Tkey << 32) |
                          (unsigned)(0xFFFFFFFFu - (unsigned)eq[jj]);
    __syncthreads();

    // bitonic ascending sort of 512 packed (key, ~idx); read reversed = jax order
    for (unsigned k = 2; k <= 512; k <<= 1)
        for (unsigned j = k >> 1; j > 0; j >>= 1) {
            if (tid < 512) {
                unsigned i = tid, ixj = i ^ j;
                if (ixj > i) {
                    unsigned long long a = sel[i], c = sel[ixj];
                    bool up = ((i & k) == 0);
                    if ((a > c) == up) { sel[i] = c; sel[ixj] = a; }
                }
            }
            __syncthreads();
        }
    if (tid < 512)
        g_idx[b * KK + tid] =
            (int)(0xFFFFFFFFu - (unsigned)(sel[511 - tid] & 0xFFFFFFFFull));
}

// ====================== big-tile GEMM: C = A @ W^T + bias =================
// 128x128 tile, 8x8 per thread, double-buffered smem. If idxp != null, the
// A rows are gathered: row r of batch b comes from gfeat[(b*NN+idxp[b*KK+r])].
#define LDP 132   // padded smem leading dim (conflict-free transposed stores)

#define G128_STS(BUF)                                                     \
    {                                                                     \
        float* as = As[BUF]; float* bs = Bs[BUF];                         \
        as[(lc + 0) * LDP + lr]      = ag0.x;                             \
        as[(lc + 1) * LDP + lr]      = ag0.y;                             \
        as[(lc + 2) * LDP + lr]      = ag0.z;                             \
        as[(lc + 3) * LDP + lr]      = ag0.w;                             \
        as[(lc + 0) * LDP + lr + 64] = ag1.x;                             \
        as[(lc + 1) * LDP + lr + 64] = ag1.y;                             \
        as[(lc + 2) * LDP + lr + 64] = ag1.z;                             \
        as[(lc + 3) * LDP + lr + 64] = ag1.w;                             \
        bs[(lc + 0) * LDP + lr]      = bg0.x;                             \
        bs[(lc + 1) * LDP + lr]      = bg0.y;                             \
        bs[(lc + 2) * LDP + lr]      = bg0.z;                             \
        bs[(lc + 3) * LDP + lr]      = bg0.w;                             \
        bs[(lc + 0) * LDP + lr + 64] = bg1.x;                             \
        bs[(lc + 1) * LDP + lr + 64] = bg1.y;                             \
        bs[(lc + 2) * LDP + lr + 64] = bg1.z;                             \
        bs[(lc + 3) * LDP + lr + 64] = bg1.w;                             \
    }

#define G128_COMPUTE(BUF)                                                 \
    _Pragma("unroll")                                                     \
    for (int k = 0; k < 16; k++) {                                        \
        float a[8], bb[8];                                                \
        *(float4*)&a[0]  = *(const float4*)&As[BUF][k * LDP + ty4];       \
        *(float4*)&a[4]  = *(const float4*)&As[BUF][k * LDP + 64 + ty4];  \
        *(float4*)&bb[0] = *(const float4*)&Bs[BUF][k * LDP + tx4];       \
        *(float4*)&bb[4] = *(const float4*)&Bs[BUF][k * LDP + 64 + tx4];  \
        _Pragma("unroll")                                                 \
        for (int i = 0; i < 8; i++)                                       \
            _Pragma("unroll")                                             \
            for (int j = 0; j < 8; j++)                                   \
                acc[i][j] = fmaf(a[i], bb[j], acc[i][j]);                 \
    }

__global__ void __launch_bounds__(256, 2)
gemm128(const float* __restrict__ A, long long strideA,
        const float* __restrict__ W,
        const float* __restrict__ bias,
        float* __restrict__ C, long long strideC,
        int Kd,
        const int* __restrict__ idxp, const float* __restrict__ gfeat) {
    const int b = blockIdx.z;
    float* Cb = C + (long long)b * strideC;
    const int N = gridDim.x * 128;

    __shared__ float As[2][16 * LDP];
    __shared__ float Bs[2][16 * LDP];

    const int tid = threadIdx.x;
    const int tx4 = (tid & 15) * 4, ty4 = (tid >> 4) * 4;
    const int row0 = blockIdx.y * 128, col0 = blockIdx.x * 128;
    const int lr = tid >> 2;             // 0..63
    const int lc = (tid & 3) << 2;       // 0,4,8,12

    const float* Ar0;
    const float* Ar1;
    if (idxp) {
        const int* ib = idxp + b * KK;
        Ar0 = gfeat + ((size_t)b * NN + ib[row0 + lr]) * Kd + lc;
        Ar1 = gfeat + ((size_t)b * NN + ib[row0 + lr + 64]) * Kd + lc;
    } else {
        const float* Ab = A + (long long)b * strideA;
        Ar0 = Ab + (long long)(row0 + lr) * Kd + lc;
        Ar1 = Ab + (long long)(row0 + lr + 64) * Kd + lc;
    }
    const float* Wr0 = W + (long long)(col0 + lr) * Kd + lc;
    const float* Wr1 = W + (long long)(col0 + lr + 64) * Kd + lc;

    float acc[8][8];
#pragma unroll
    for (int i = 0; i < 8; i++)
#pragma unroll
        for (int j = 0; j < 8; j++) acc[i][j] = 0.f;

    float4 ag0 = *(const float4*)(Ar0);
    float4 ag1 = *(const float4*)(Ar1);
    float4 bg0 = *(const float4*)(Wr0);
    float4 bg1 = *(const float4*)(Wr1);
    G128_STS(0)
    __syncthreads();

    int buf = 0;
    for (int k0 = 16; k0 < Kd; k0 += 16) {
        ag0 = *(const float4*)(Ar0 + k0);
        ag1 = *(const float4*)(Ar1 + k0);
        bg0 = *(const float4*)(Wr0 + k0);
        bg1 = *(const float4*)(Wr1 + k0);
        G128_COMPUTE(buf)
        G128_STS(buf ^ 1)
        __syncthreads();
        buf ^= 1;
    }
    G128_COMPUTE(buf)

    // epilogue: bias + store (two float4 per row)
#pragma unroll
    for (int i = 0; i < 8; i++) {
        int m = row0 + ty4 + (i & 3) + ((i >= 4) ? 64 : 0);
        float4 v0, v1;
        v0.x = acc[i][0] + bias[col0 + tx4 + 0];
        v0.y = acc[i][1] + bias[col0 + tx4 + 1];
        v0.z = acc[i][2] + bias[col0 + tx4 + 2];
        v0.w = acc[i][3] + bias[col0 + tx4 + 3];
        v1.x = acc[i][4] + bias[col0 + 64 + tx4 + 0];
        v1.y = acc[i][5] + bias[col0 + 64 + tx4 + 1];
        v1.z = acc[i][6] + bias[col0 + 64 + tx4 + 2];
        v1.w = acc[i][7] + bias[col0 + 64 + tx4 + 3];
        *(float4*)(Cb + (long long)m * N + col0 + tx4)      = v0;
        *(float4*)(Cb + (long long)m * N + col0 + 64 + tx4) = v1;
    }
}

// ---------------- small NT GEMM (64x64 tile) with remap/residual/activation --
// amode:   0 = A row m contiguous, 1 = A row m at ((m>>4)*KK + (m&15)) (q remap)
// resmode: 0 = none, 1 = res[m*N+n], 2 = res[((m>>4)*KK + (m&15))*EE + n]
// act:     0 = none, 1 = exact GELU applied to (acc+bias) before residual add
__global__ void __launch_bounds__(256)
gemm_nt_bias(const float* __restrict__ A, long long strideA, int amode,
             const float* __restrict__ W,
             const float* __restrict__ bias,
             const float* __restrict__ res, int resmode, int act,
             float* __restrict__ C, long long strideC,
             int M, int N, int Kd) {
    const int b = blockIdx.z;
    A += (long long)b * strideA;
    C += (long long)b * strideC;

    __shared__ float As[16][64];
    __shared__ float Bs[16][64];

    const int tid = threadIdx.x;          // 256
    const int tx = tid & 15, ty = tid >> 4;
    const int row0 = blockIdx.y * 64, col0 = blockIdx.x * 64;
    const int ar = tid >> 2, ac = (tid & 3) << 2;

    long long arow = row0 + ar;
    if (amode == 1) arow = (long long)((int)arow >> 4) * KK + ((int)arow & 15);

    float acc[4][4];
#pragma unroll
    for (int i = 0; i < 4; i++)
#pragma unroll
        for (int j = 0; j < 4; j++) acc[i][j] = 0.f;

    for (int k0 = 0; k0 < Kd; k0 += 16) {
        float4 av = make_float4(0.f, 0.f, 0.f, 0.f);
        float4 bv = make_float4(0.f, 0.f, 0.f, 0.f);
        if (row0 + ar < M) av = *(const float4*)(A + arow * Kd + k0 + ac);
        if (col0 + ar < N) bv = *(const float4*)(W + (long long)(col0 + ar) * Kd + k0 + ac);
        __syncthreads();
        As[ac + 0][ar] = av.x; As[ac + 1][ar] = av.y;
        As[ac + 2][ar] = av.z; As[ac + 3][ar] = av.w;
        Bs[ac + 0][ar] = bv.x; Bs[ac + 1][ar] = bv.y;
        Bs[ac + 2][ar] = bv.z; Bs[ac + 3][ar] = bv.w;
        __syncthreads();
#pragma unroll
        for (int k = 0; k < 16; k++) {
            float a[4], bb[4];
            *(float4*)a  = *(const float4*)&As[k][ty << 2];
            *(float4*)bb = *(const float4*)&Bs[k][tx << 2];
#pragma unroll
            for (int i = 0; i < 4; i++)
#pragma unroll
                for (int j = 0; j < 4; j++)
                    acc[i][j] = fmaf(a[i], bb[j], acc[i][j]);
        }
    }
#pragma unroll
    for (int i = 0; i < 4; i++) {
        int m = row0 + (ty << 2) + i;
        if (m < M) {
#pragma unroll
            for (int j = 0; j < 4; j++) {
                int n = col0 + (tx << 2) + j;
                float t = acc[i][j] + bias[n];
                if (act) t = 0.5f * t * (1.f + erff(t * 0.70710678118654752f));
                if (resmode == 1)      t += res[(long long)m * N + n];
                else if (resmode == 2) t += res[((long long)(m >> 4) * KK + (m & 15)) * EE + n];
                C[(long long)m * N + n] = t;
            }
        }
    }
}

// ---------------- attention for 16 queries, per (head, batch) ----------------
__global__ void __launch_bounds__(256) attn_kernel() {
    const int h = blockIdx.x, b = blockIdx.y;
    const float* qb = g_q + ((size_t)b * TT) * EE + h * 64;
    const float* kb = g_kv + (size_t)b * KK * 2 * EE + h * 64;
    const float* vb = kb + EE;

    __shared__ float qs[TT][64];
    __shared__ float lg[TT][KK];
    __shared__ float vs[32][68];
    const int tid = threadIdx.x;  // 256

    for (int i = tid; i < TT * 64; i += 256) {
        int t = i >> 6, d = i & 63;
        qs[t][d] = qb[t * EE + d] * 0.125f;   // 1/sqrt(64)
    }
    __syncthreads();

    // logits
    for (int kk = tid; kk < KK; kk += 256) {
        const float4* krow = (const float4*)(kb + (size_t)kk * (2 * EE));
        float acc[TT];
#pragma unroll
        for (int t = 0; t < TT; t++) acc[t] = 0.f;
#pragma unroll
        for (int d4 = 0; d4 < 16; d4++) {
            float4 k4 = krow[d4];
#pragma unroll
            for (int t = 0; t < TT; t++) {
                acc[t] += qs[t][d4 * 4 + 0] * k4.x + qs[t][d4 * 4 + 1] * k4.y +
                          qs[t][d4 * 4 + 2] * k4.z + qs[t][d4 * 4 + 3] * k4.w;
            }
        }
#pragma unroll
        for (int t = 0; t < TT; t++) lg[t][kk] = acc[t];
    }
    __syncthreads();

    // softmax: each of 8 warps owns 2 rows
    const int w = tid >> 5, lane = tid & 31;
    for (int t = w; t < TT; t += 8) {
        float m = -1e30f;
        for (int i = lane; i < KK; i += 32) m = fmaxf(m, lg[t][i]);
#pragma unroll
        for (int o = 16; o > 0; o >>= 1) m = fmaxf(m, __shfl_xor_sync(0xFFFFFFFFu, m, o));
        float ssum = 0.f;
        for (int i = lane; i < KK; i += 32) {
            float e = __expf(lg[t][i] - m);
            lg[t][i] = e; ssum += e;
        }
#pragma unroll
        for (int o = 16; o > 0; o >>= 1) ssum += __shfl_xor_sync(0xFFFFFFFFu, ssum, o);
        float inv = 1.f / ssum;
        for (int i = lane; i < KK; i += 32) lg[t][i] *= inv;
    }

    // o = attn @ v  via 32-row V tiles in smem
    const int d = tid & 63, tg = tid >> 6;           // tg in 0..3
    const int vr = tid >> 4;                          // 0..15
    const int vc = (tid & 15) * 4;
    float acc4[4] = {0.f, 0.f, 0.f, 0.f};
    for (int kk0 = 0; kk0 < KK; kk0 += 32) {
        __syncthreads();
        const float* vrow = vb + (size_t)(kk0 + vr) * (2 * EE) + vc;
        float4 v0 = *(const float4*)(vrow);
        float4 v1 = *(const float4*)(vrow + (size_t)16 * 2 * EE);
        *(float4*)&vs[vr][vc]      = v0;
        *(float4*)&vs[vr + 16][vc] = v1;
        __syncthreads();
#pragma unroll
        for (int r = 0; r < 32; r++) {
            float v = vs[r][d];
#pragma unroll
            for (int i = 0; i < 4; i++)
                acc4[i] = fmaf(lg[tg + i * 4][kk0 + r], v, acc4[i]);
        }
    }
#pragma unroll
    for (int i = 0; i < 4; i++)
        g_o[((size_t)b * TT + tg + i * 4) * EE + h * 64 + d] = acc4[i];
}

// ---------------- layernorm over rows of g_y -> g_z ----------------
__global__ void __launch_bounds__(128) ln_kernel(const float* __restrict__ lng,
                                                 const float* __restrict__ lnb) {
    const int row = blockIdx.x;   // 256 rows
    const int tid = threadIdx.x;  // 128
    const float* yr = g_y + (size_t)row * EE;
    float* zr = g_z + (size_t)row * EE;
    __shared__ float red[4];

    float v[4];
#pragma unroll
    for (int u = 0; u < 4; u++) v[u] = yr[tid + u * 128];

    float s = v[0] + v[1] + v[2] + v[3];
#pragma unroll
    for (int o = 16; o > 0; o >>= 1) s += __shfl_xor_sync(0xFFFFFFFFu, s, o);
    if ((tid & 31) == 0) red[tid >> 5] = s;
    __syncthreads();
    const float mu = (red[0] + red[1] + red[2] + red[3]) / EE;
    __syncthreads();

    float q = 0.f;
#pragma unroll
    for (int u = 0; u < 4; u++) { float dlt = v[u] - mu; q += dlt * dlt; }
#pragma unroll
    for (int o = 16; o > 0; o >>= 1) q += __shfl_xor_sync(0xFFFFFFFFu, q, o);
    if ((tid & 31) == 0) red[tid >> 5] = q;
    __syncthreads();
    const float rstd = rsqrtf((red[0] + red[1] + red[2] + red[3]) / EE + 1e-5f);

#pragma unroll
    for (int u = 0; u < 4; u++) {
        int e = tid + u * 128;
        zr[e] = (v[u] - mu) * rstd * lng[e] + lnb[e];
    }
}

// ---------------- launch ----------------
extern "C" void kernel_launch(void* const* d_in, const int* in_sizes, int n_in,
                              void* d_out, int out_size) {
    (void)in_sizes; (void)n_in; (void)out_size;
    const float* feats  = (const float*)d_in[0];
    const float* scores = (const float*)d_in[1];
    const float* proj_w = (const float*)d_in[2];
    const float* proj_b = (const float*)d_in[3];
    const float* in_w   = (const float*)d_in[4];
    const float* in_b   = (const float*)d_in[5];
    const float* out_w  = (const float*)d_in[6];
    const float* out_b  = (const float*)d_in[7];
    const float* ln_g   = (const float*)d_in[8];
    const float* ln_b   = (const float*)d_in[9];
    const float* ffn_w  = (const float*)d_in[10];
    const float* ffn_b  = (const float*)d_in[11];
    float* out = (float*)d_out;

    float *px, *pkv, *pq, *po, *py, *pz;
    int* pidx;
    cudaGetSymbolAddress((void**)&px,   g_x);
    cudaGetSymbolAddress((void**)&pkv,  g_kv);
    cudaGetSymbolAddress((void**)&pq,   g_q);
    cudaGetSymbolAddress((void**)&po,   g_o);
    cudaGetSymbolAddress((void**)&py,   g_y);
    cudaGetSymbolAddress((void**)&pz,   g_z);
    cudaGetSymbolAddress((void**)&pidx, g_idx);

    static int smem_set = 0;
    if (!smem_set) {
        cudaFuncSetAttribute(topk_kernel,
                             cudaFuncAttributeMaxDynamicSharedMemorySize,
                             NN * (int)sizeof(unsigned));
        smem_set = 1;
    }

    topk_kernel<<<BB, 1024, NN * sizeof(unsigned)>>>(scores);

    // x = feats[idx] @ proj_w^T + proj_b          [512 x 512] per batch (fused gather)
    gemm128<<<dim3(EE / 128, KK / 128, BB), 256>>>(
        nullptr, 0LL, proj_w, proj_b, px, (long long)KK * EE, DD, pidx, feats);
    // kv = x @ [Wk;Wv]^T + b                      [512 x 1024] per batch
    gemm128<<<dim3(2 * EE / 128, KK / 128, BB), 256>>>(
        px, (long long)KK * EE, in_w + EE * EE, in_b + EE, pkv,
        (long long)KK * 2 * EE, EE, nullptr, nullptr);
    // q = x[:, :16] @ Wq^T + bq                   [256 x 512] flat (row-remapped A)
    gemm_nt_bias<<<dim3(EE / 64, (BB * TT) / 64, 1), 256>>>(
        px, 0LL, 1, in_w, in_b, nullptr, 0, 0, pq, 0LL, BB * TT, EE, EE);

    attn_kernel<<<dim3(HH, BB), 256>>>();

    // y = x[:, :16] + o @ Wo^T + bo               [256 x 512] flat
    gemm_nt_bias<<<dim3(EE / 64, (BB * TT) / 64, 1), 256>>>(
        po, 0LL, 0, out_w, out_b, px, 2, 0, py, 0LL, BB * TT, EE, EE);
    // z = layernorm(y)
    ln_kernel<<<BB * TT, 128>>>(ln_g, ln_b);
    // out = z + gelu(z @ Wf^T + bf)
    gemm_nt_bias<<<dim3(EE / 64, (BB * TT) / 64, 1), 256>>>(
        pz, 0LL, 0, ffn_w, ffn_b, pz, 1, 1, out, 0LL, BB * TT, EE, EE);
}

// round 6
// speedup vs baseline: 1.7199x; 1.2164x over previous
#include <cuda_runtime.h>
#include <cstdint>
#include <math.h>

#define BB 16
#define NN 32768
#define DD 256
#define EE 512
#define HH 8
#define KK 512
#define TT 16

// ---------------- device scratch (no allocations allowed) ----------------
__device__ float g_x[BB * KK * EE];          // projected x     16 MB
__device__ float g_kv[BB * KK * 2 * EE];     // k|v concat      32 MB
__device__ float g_o[BB * TT * EE];          // attn out (256 x 512 flat)
__device__ float g_z[BB * TT * EE];          // post layernorm
__device__ float g_part[4 * BB * TT * EE];   // split-K partials (2 MB)
__device__ int   g_idx[BB * KK];             // top-k indices

// order-preserving float->uint key (bigger key == bigger float)
__device__ __forceinline__ unsigned fkey(float f) {
    unsigned u = __float_as_uint(f);
    return (u & 0x80000000u) ? ~u : (u | 0x80000000u);
}

// ---------------- top-K: smem-resident keys, radix select + bitonic sort ----
extern __shared__ unsigned skeys[];   // NN unsigned = 128 KB dynamic smem

__global__ void __launch_bounds__(1024) topk_kernel(const float* __restrict__ scores) {
    const int b = blockIdx.x;
    const float* s = scores + (size_t)b * NN;
    const int tid = threadIdx.x;  // 1024 threads

    __shared__ unsigned hist[256];
    __shared__ unsigned sh_prefix, sh_mask, sh_remk;
    __shared__ int sh_cntgt, sh_cnteq;
    __shared__ unsigned long long sel[512];
    __shared__ int eq[1024];

    if (tid == 0) { sh_prefix = 0u; sh_mask = 0u; sh_remk = KK; }
    if (tid < 256) hist[tid] = 0u;
    __syncthreads();

    // load + first-pass histogram (prefix empty, counts all)
    for (int i = tid; i < NN; i += 1024) {
        unsigned k = fkey(__ldg(&s[i]));
        skeys[i] = k;
        atomicAdd(&hist[k >> 24], 1u);
    }
    __syncthreads();

    for (int pass = 0; pass < 4; pass++) {
        const int shift = 24 - pass * 8;
        if (tid == 0) {
            unsigned remk = sh_remk, acc = 0u;
            int d;
            for (d = 255; d >= 0; d--) {
                if (acc + hist[d] >= remk) break;
                acc += hist[d];
            }
            sh_remk  = remk - acc;
            sh_prefix = sh_prefix | ((unsigned)d << shift);
            sh_mask   = sh_mask | (0xFFu << shift);
            sh_cntgt = 0; sh_cnteq = 0;
        }
        __syncthreads();
        if (pass == 3) break;
        // next-pass histogram over smem keys
        if (tid < 256) hist[tid] = 0u;
        __syncthreads();
        const unsigned prefix = sh_prefix, mask = sh_mask;
        const int nshift = shift - 8;
        for (int i = tid; i < NN; i += 1024) {
            unsigned k = skeys[i];
            if ((k & mask) == prefix) atomicAdd(&hist[(k >> nshift) & 255u], 1u);
        }
        __syncthreads();
    }

    const unsigned Tkey = sh_prefix;
    const int remk = (int)sh_remk;

    // gather: strictly-greater always in; equals collected for index tie-break
    for (int i = tid; i < NN; i += 1024) {
        unsigned k = skeys[i];
        if (k > Tkey) {
            int p = atomicAdd(&sh_cntgt, 1);
            sel[p] = ((unsigned long long)k << 32) | (unsigned)(0xFFFFFFFFu - (unsigned)i);
        } else if (k == Tkey) {
            int p = atomicAdd(&sh_cnteq, 1);
            if (p < 1024) eq[p] = i;
        }
    }
    __syncthreads();
    const int cntgt = sh_cntgt;
    const int cnteq = min(sh_cnteq, 1024);

    // sort equal-key indices ascending (ties -> lower index first)
    if (tid >= cnteq) eq[tid] = 0x7FFFFFFF;
    __syncthreads();
    for (unsigned k = 2; k <= 1024; k <<= 1)
        for (unsigned j = k >> 1; j > 0; j >>= 1) {
            unsigned i = tid, ixj = i ^ j;
            if (ixj > i) {
                int a = eq[i], c = eq[ixj];
                bool up = ((i & k) == 0);
                if ((a > c) == up) { eq[i] = c; eq[ixj] = a; }
            }
            __syncthreads();
        }
    for (int jj = tid; jj < remk; jj += 1024)
        sel[cntgt + jj] = ((unsigned long long)Tkey << 32) |
                          (unsigned)(0xFFFFFFFFu - (unsigned)eq[jj]);
    __syncthreads();

    // bitonic ascending sort of 512 packed (key, ~idx); read reversed = jax order
    for (unsigned k = 2; k <= 512; k <<= 1)
        for (unsigned j = k >> 1; j > 0; j >>= 1) {
            if (tid < 512) {
                unsigned i = tid, ixj = i ^ j;
                if (ixj > i) {
                    unsigned long long a = sel[i], c = sel[ixj];
                    bool up = ((i & k) == 0);
                    if ((a > c) == up) { sel[i] = c; sel[ixj] = a; }
                }
            }
            __syncthreads();
        }
    if (tid < 512)
        g_idx[b * KK + tid] =
            (int)(0xFFFFFFFFu - (unsigned)(sel[511 - tid] & 0xFFFFFFFFull));
}

// ====================== big-tile GEMM: C = A @ W^T + bias =================
// 128x128 tile, 8x8 per thread, double-buffered smem. If idxp != null, the
// A rows are gathered: row r of batch b comes from gfeat[(b*NN+idxp[b*KK+r])].
#define LDP 132   // padded smem leading dim (conflict-free transposed stores)

#define G128_STS(BUF)                                                     \
    {                                                                     \
        float* as = As[BUF]; float* bs = Bs[BUF];                         \
        as[(lc + 0) * LDP + lr]      = ag0.x;                             \
        as[(lc + 1) * LDP + lr]      = ag0.y;                             \
        as[(lc + 2) * LDP + lr]      = ag0.z;                             \
        as[(lc + 3) * LDP + lr]      = ag0.w;                             \
        as[(lc + 0) * LDP + lr + 64] = ag1.x;                             \
        as[(lc + 1) * LDP + lr + 64] = ag1.y;                             \
        as[(lc + 2) * LDP + lr + 64] = ag1.z;                             \
        as[(lc + 3) * LDP + lr + 64] = ag1.w;                             \
        bs[(lc + 0) * LDP + lr]      = bg0.x;                             \
        bs[(lc + 1) * LDP + lr]      = bg0.y;                             \
        bs[(lc + 2) * LDP + lr]      = bg0.z;                             \
        bs[(lc + 3) * LDP + lr]      = bg0.w;                             \
        bs[(lc + 0) * LDP + lr + 64] = bg1.x;                             \
        bs[(lc + 1) * LDP + lr + 64] = bg1.y;                             \
        bs[(lc + 2) * LDP + lr + 64] = bg1.z;                             \
        bs[(lc + 3) * LDP + lr + 64] = bg1.w;                             \
    }

#define G128_COMPUTE(BUF)                                                 \
    _Pragma("unroll")                                                     \
    for (int k = 0; k < 16; k++) {                                        \
        float a[8], bb[8];                                                \
        *(float4*)&a[0]  = *(const float4*)&As[BUF][k * LDP + ty4];       \
        *(float4*)&a[4]  = *(const float4*)&As[BUF][k * LDP + 64 + ty4];  \
        *(float4*)&bb[0] = *(const float4*)&Bs[BUF][k * LDP + tx4];       \
        *(float4*)&bb[4] = *(const float4*)&Bs[BUF][k * LDP + 64 + tx4];  \
        _Pragma("unroll")                                                 \
        for (int i = 0; i < 8; i++)                                       \
            _Pragma("unroll")                                             \
            for (int j = 0; j < 8; j++)                                   \
                acc[i][j] = fmaf(a[i], bb[j], acc[i][j]);                 \
    }

__global__ void __launch_bounds__(256, 2)
gemm128(const float* __restrict__ A, long long strideA,
        const float* __restrict__ W,
        const float* __restrict__ bias,
        float* __restrict__ C, long long strideC,
        int Kd,
        const int* __restrict__ idxp, const float* __restrict__ gfeat) {
    const int b = blockIdx.z;
    float* Cb = C + (long long)b * strideC;
    const int N = gridDim.x * 128;

    __shared__ __align__(16) float As[2][16 * LDP];
    __shared__ __align__(16) float Bs[2][16 * LDP];

    const int tid = threadIdx.x;
    const int tx4 = (tid & 15) * 4, ty4 = (tid >> 4) * 4;
    const int row0 = blockIdx.y * 128, col0 = blockIdx.x * 128;
    const int lr = tid >> 2;             // 0..63
    const int lc = (tid & 3) << 2;       // 0,4,8,12

    const float* Ar0;
    const float* Ar1;
    if (idxp) {
        const int* ib = idxp + b * KK;
        Ar0 = gfeat + ((size_t)b * NN + ib[row0 + lr]) * Kd + lc;
        Ar1 = gfeat + ((size_t)b * NN + ib[row0 + lr + 64]) * Kd + lc;
    } else {
        const float* Ab = A + (long long)b * strideA;
        Ar0 = Ab + (long long)(row0 + lr) * Kd + lc;
        Ar1 = Ab + (long long)(row0 + lr + 64) * Kd + lc;
    }
    const float* Wr0 = W + (long long)(col0 + lr) * Kd + lc;
    const float* Wr1 = W + (long long)(col0 + lr + 64) * Kd + lc;

    float acc[8][8];
#pragma unroll
    for (int i = 0; i < 8; i++)
#pragma unroll
        for (int j = 0; j < 8; j++) acc[i][j] = 0.f;

    float4 ag0 = *(const float4*)(Ar0);
    float4 ag1 = *(const float4*)(Ar1);
    float4 bg0 = *(const float4*)(Wr0);
    float4 bg1 = *(const float4*)(Wr1);
    G128_STS(0)
    __syncthreads();

    int buf = 0;
    for (int k0 = 16; k0 < Kd; k0 += 16) {
        ag0 = *(const float4*)(Ar0 + k0);
        ag1 = *(const float4*)(Ar1 + k0);
        bg0 = *(const float4*)(Wr0 + k0);
        bg1 = *(const float4*)(Wr1 + k0);
        G128_COMPUTE(buf)
        G128_STS(buf ^ 1)
        __syncthreads();
        buf ^= 1;
    }
    G128_COMPUTE(buf)

    // epilogue: bias + store (two float4 per row)
#pragma unroll
    for (int i = 0; i < 8; i++) {
        int m = row0 + ty4 + (i & 3) + ((i >= 4) ? 64 : 0);
        float4 v0, v1;
        v0.x = acc[i][0] + bias[col0 + tx4 + 0];
        v0.y = acc[i][1] + bias[col0 + tx4 + 1];
        v0.z = acc[i][2] + bias[col0 + tx4 + 2];
        v0.w = acc[i][3] + bias[col0 + tx4 + 3];
        v1.x = acc[i][4] + bias[col0 + 64 + tx4 + 0];
        v1.y = acc[i][5] + bias[col0 + 64 + tx4 + 1];
        v1.z = acc[i][6] + bias[col0 + 64 + tx4 + 2];
        v1.w = acc[i][7] + bias[col0 + 64 + tx4 + 3];
        *(float4*)(Cb + (long long)m * N + col0 + tx4)      = v0;
        *(float4*)(Cb + (long long)m * N + col0 + 64 + tx4) = v1;
    }
}

// ============ split-K GEMM partials: part[kc] = A @ W^T (chunk kc) =========
// M=256, N=512, K=512 split into 4 chunks of 128. Grid (8, 4, 4), 256 thr.
#define SKP 68

#define SK_STS(BUF)                                                       \
    {                                                                     \
        float* as = As[BUF]; float* bs = Bs[BUF];                         \
        as[(lc + 0) * SKP + lr] = av.x;                                   \
        as[(lc + 1) * SKP + lr] = av.y;                                   \
        as[(lc + 2) * SKP + lr] = av.z;                                   \
        as[(lc + 3) * SKP + lr] = av.w;                                   \
        bs[(lc + 0) * SKP + lr] = bv.x;                                   \
        bs[(lc + 1) * SKP + lr] = bv.y;                                   \
        bs[(lc + 2) * SKP + lr] = bv.z;                                   \
        bs[(lc + 3) * SKP + lr] = bv.w;                                   \
    }

#define SK_COMPUTE(BUF)                                                   \
    _Pragma("unroll")                                                     \
    for (int k = 0; k < 16; k++) {                                        \
        float a[4], bb[4];                                                \
        *(float4*)a  = *(const float4*)&As[BUF][k * SKP + ty4];           \
        *(float4*)bb = *(const float4*)&Bs[BUF][k * SKP + tx4];           \
        _Pragma("unroll")                                                 \
        for (int i = 0; i < 4; i++)                                       \
            _Pragma("unroll")                                             \
            for (int j = 0; j < 4; j++)                                   \
                acc[i][j] = fmaf(a[i], bb[j], acc[i][j]);                 \
    }

__global__ void __launch_bounds__(256)
gemm_splitk(const float* __restrict__ A, const float* __restrict__ W,
            float* __restrict__ part) {
    const int kc = blockIdx.z;                       // 0..3
    const int row0 = blockIdx.y * 64, col0 = blockIdx.x * 64;
    const int tid = threadIdx.x;
    const int tx4 = (tid & 15) * 4, ty4 = (tid >> 4) * 4;
    const int lr = tid >> 2, lc = (tid & 3) << 2;

    __shared__ __align__(16) float As[2][16 * SKP];
    __shared__ __align__(16) float Bs[2][16 * SKP];

    const float* Ar = A + (size_t)(row0 + lr) * EE + kc * 128 + lc;
    const float* Wr = W + (size_t)(col0 + lr) * EE + kc * 128 + lc;

    float acc[4][4];
#pragma unroll
    for (int i = 0; i < 4; i++)
#pragma unroll
        for (int j = 0; j < 4; j++) acc[i][j] = 0.f;

    float4 av = *(const float4*)(Ar);
    float4 bv = *(const float4*)(Wr);
    SK_STS(0)
    __syncthreads();

    int buf = 0;
#pragma unroll
    for (int k0 = 16; k0 < 128; k0 += 16) {
        av = *(const float4*)(Ar + k0);
        bv = *(const float4*)(Wr + k0);
        SK_COMPUTE(buf)
        SK_STS(buf ^ 1)
        __syncthreads();
        buf ^= 1;
    }
    SK_COMPUTE(buf)

    float* pp = part + (size_t)kc * (BB * TT * EE);
#pragma unroll
    for (int i = 0; i < 4; i++) {
        float4 v;
        v.x = acc[i][0]; v.y = acc[i][1]; v.z = acc[i][2]; v.w = acc[i][3];
        *(float4*)(pp + (size_t)(row0 + ty4 + i) * EE + col0 + tx4) = v;
    }
}

// ---------------- fused q-proj + attention, per (head, batch) ---------------
__global__ void __launch_bounds__(256)
qattn_kernel(const float* __restrict__ Wq, const float* __restrict__ bq) {
    const int h = blockIdx.x, b = blockIdx.y;
    const float* kb = g_kv + (size_t)b * KK * 2 * EE + h * 64;
    const float* vb = kb + EE;

    __shared__ float buf[TT * EE];        // x rows first, then logits
    __shared__ float qs[TT][64];
    __shared__ float vs[32][68];
    const int tid = threadIdx.x;  // 256
    float (*xs)[EE] = (float(*)[EE])buf;
    float (*lg)[KK] = (float(*)[KK])buf;

    // stage 1: load x[b, :16, :] into smem
    {
        const float4* xb4 = (const float4*)(g_x + (size_t)b * KK * EE);
        float4* b4 = (float4*)buf;
        // first 16 rows of x are contiguous (row stride EE)
        for (int i = tid; i < TT * EE / 4; i += 256) b4[i] = xb4[i];
    }
    __syncthreads();

    // stage 2: q[t][d] = (x[t] . Wq[h*64+d] + bq) / 8   (smem reads broadcast)
    const int d = tid & 63, tg = tid >> 6;
    {
        const float4* wrow = (const float4*)(Wq + (size_t)(h * 64 + d) * EE);
        float acc[4] = {0.f, 0.f, 0.f, 0.f};
        for (int e4 = 0; e4 < EE / 4; e4++) {
            float4 w = wrow[e4];
#pragma unroll
            for (int i = 0; i < 4; i++) {
                const float* xr = &xs[tg + i * 4][e4 * 4];
                acc[i] += xr[0] * w.x + xr[1] * w.y + xr[2] * w.z + xr[3] * w.w;
            }
        }
        const float bias = bq[h * 64 + d];
#pragma unroll
        for (int i = 0; i < 4; i++)
            qs[tg + i * 4][d] = (acc[i] + bias) * 0.125f;
    }
    __syncthreads();   // x fully consumed; buf can be reused for logits

    // stage 3: logits
    for (int kk = tid; kk < KK; kk += 256) {
        const float4* krow = (const float4*)(kb + (size_t)kk * (2 * EE));
        float acc[TT];
#pragma unroll
        for (int t = 0; t < TT; t++) acc[t] = 0.f;
#pragma unroll
        for (int d4 = 0; d4 < 16; d4++) {
            float4 k4 = krow[d4];
#pragma unroll
            for (int t = 0; t < TT; t++) {
                acc[t] += qs[t][d4 * 4 + 0] * k4.x + qs[t][d4 * 4 + 1] * k4.y +
                          qs[t][d4 * 4 + 2] * k4.z + qs[t][d4 * 4 + 3] * k4.w;
            }
        }
#pragma unroll
        for (int t = 0; t < TT; t++) lg[t][kk] = acc[t];
    }
    __syncthreads();

    // stage 4: softmax (each of 8 warps owns 2 rows)
    const int w = tid >> 5, lane = tid & 31;
    for (int t = w; t < TT; t += 8) {
        float m = -1e30f;
        for (int i = lane; i < KK; i += 32) m = fmaxf(m, lg[t][i]);
#pragma unroll
        for (int o = 16; o > 0; o >>= 1) m = fmaxf(m, __shfl_xor_sync(0xFFFFFFFFu, m, o));
        float ssum = 0.f;
        for (int i = lane; i < KK; i += 32) {
            float e = __expf(lg[t][i] - m);
            lg[t][i] = e; ssum += e;
        }
#pragma unroll
        for (int o = 16; o > 0; o >>= 1) ssum += __shfl_xor_sync(0xFFFFFFFFu, ssum, o);
        float inv = 1.f / ssum;
        for (int i = lane; i < KK; i += 32) lg[t][i] *= inv;
    }

    // stage 5: o = attn @ v  via 32-row V tiles in smem
    const int vr = tid >> 4;                 // 0..15
    const int vc = (tid & 15) * 4;
    float acc4[4] = {0.f, 0.f, 0.f, 0.f};
    for (int kk0 = 0; kk0 < KK; kk0 += 32) {
        __syncthreads();
        const float* vrow = vb + (size_t)(kk0 + vr) * (2 * EE) + vc;
        float4 v0 = *(const float4*)(vrow);
        float4 v1 = *(const float4*)(vrow + (size_t)16 * 2 * EE);
        *(float4*)&vs[vr][vc]      = v0;
        *(float4*)&vs[vr + 16][vc] = v1;
        __syncthreads();
#pragma unroll
        for (int r = 0; r < 32; r++) {
            float v = vs[r][d];
#pragma unroll
            for (int i = 0; i < 4; i++)
                acc4[i] = fmaf(lg[tg + i * 4][kk0 + r], v, acc4[i]);
        }
    }
#pragma unroll
    for (int i = 0; i < 4; i++)
        g_o[((size_t)b * TT + tg + i * 4) * EE + h * 64 + d] = acc4[i];
}

// -------- epilogue 1: y = sum(part) + bo + x_res ; z = LN(y) --------------
__global__ void __launch_bounds__(128)
epi_ln(const float* __restrict__ bo,
       const float* __restrict__ lng, const float* __restrict__ lnb) {
    const int row = blockIdx.x;   // 0..255
    const int tid = threadIdx.x;  // 128
    const float* xres = g_x + ((size_t)(row >> 4) * KK + (row & 15)) * EE;
    float* zr = g_z + (size_t)row * EE;
    __shared__ float red[4];

    float v[4];
#pragma unroll
    for (int u = 0; u < 4; u++) {
        int e = tid + u * 128;
        size_t o = (size_t)row * EE + e;
        float s = g_part[o] + g_part[o + 1 * BB * TT * EE] +
                  g_part[o + 2 * BB * TT * EE] + g_part[o + 3 * BB * TT * EE];
        v[u] = s + bo[e] + xres[e];
    }

    float s = v[0] + v[1] + v[2] + v[3];
#pragma unroll
    for (int o = 16; o > 0; o >>= 1) s += __shfl_xor_sync(0xFFFFFFFFu, s, o);
    if ((tid & 31) == 0) red[tid >> 5] = s;
    __syncthreads();
    const float mu = (red[0] + red[1] + red[2] + red[3]) / EE;
    __syncthreads();

    float q = 0.f;
#pragma unroll
    for (int u = 0; u < 4; u++) { float dlt = v[u] - mu; q += dlt * dlt; }
#pragma unroll
    for (int o = 16; o > 0; o >>= 1) q += __shfl_xor_sync(0xFFFFFFFFu, q, o);
    if ((tid & 31) == 0) red[tid >> 5] = q;
    __syncthreads();
    const float rstd = rsqrtf((red[0] + red[1] + red[2] + red[3]) / EE + 1e-5f);

#pragma unroll
    for (int u = 0; u < 4; u++) {
        int e = tid + u * 128;
        zr[e] = (v[u] - mu) * rstd * lng[e] + lnb[e];
    }
}

// -------- epilogue 2: out = z + gelu(sum(part) + bf) ----------------------
__global__ void __launch_bounds__(128)
epi_ffn(const float* __restrict__ bf, float* __restrict__ out) {
    const int row = blockIdx.x;
    const int tid = threadIdx.x;
    const float* zr = g_z + (size_t)row * EE;
    float* outp = out + (size_t)row * EE;
#pragma unroll
    for (int u = 0; u < 4; u++) {
        int e = tid + u * 128;
        size_t o = (size_t)row * EE + e;
        float t = g_part[o] + g_part[o + 1 * BB * TT * EE] +
                  g_part[o + 2 * BB * TT * EE] + g_part[o + 3 * BB * TT * EE] +
                  bf[e];
        float g = 0.5f * t * (1.f + erff(t * 0.70710678118654752f));
        outp[e] = zr[e] + g;
    }
}

// ---------------- launch ----------------
extern "C" void kernel_launch(void* const* d_in, const int* in_sizes, int n_in,
                              void* d_out, int out_size) {
    (void)in_sizes; (void)n_in; (void)out_size;
    const float* feats  = (const float*)d_in[0];
    const float* scores = (const float*)d_in[1];
    const float* proj_w = (const float*)d_in[2];
    const float* proj_b = (const float*)d_in[3];
    const float* in_w   = (const float*)d_in[4];
    const float* in_b   = (const float*)d_in[5];
    const float* out_w  = (const float*)d_in[6];
    const float* out_b  = (const float*)d_in[7];
    const float* ln_g   = (const float*)d_in[8];
    const float* ln_b   = (const float*)d_in[9];
    const float* ffn_w  = (const float*)d_in[10];
    const float* ffn_b  = (const float*)d_in[11];
    float* out = (float*)d_out;

    float *px, *pkv, *po, *pz, *ppart;
    int* pidx;
    cudaGetSymbolAddress((void**)&px,    g_x);
    cudaGetSymbolAddress((void**)&pkv,   g_kv);
    cudaGetSymbolAddress((void**)&po,    g_o);
    cudaGetSymbolAddress((void**)&pz,    g_z);
    cudaGetSymbolAddress((void**)&ppart, g_part);
    cudaGetSymbolAddress((void**)&pidx,  g_idx);

    static int smem_set = 0;
    if (!smem_set) {
        cudaFuncSetAttribute(topk_kernel,
                             cudaFuncAttributeMaxDynamicSharedMemorySize,
                             NN * (int)sizeof(unsigned));
        smem_set = 1;
    }

    topk_kernel<<<BB, 1024, NN * sizeof(unsigned)>>>(scores);

    // x = feats[idx] @ proj_w^T + proj_b          [512 x 512] per batch (fused gather)
    gemm128<<<dim3(EE / 128, KK / 128, BB), 256>>>(
        nullptr, 0LL, proj_w, proj_b, px, (long long)KK * EE, DD, pidx, feats);
    // kv = x @ [Wk;Wv]^T + b                      [512 x 1024] per batch
    gemm128<<<dim3(2 * EE / 128, KK / 128, BB), 256>>>(
        px, (long long)KK * EE, in_w + EE * EE, in_b + EE, pkv,
        (long long)KK * 2 * EE, EE, nullptr, nullptr);

    // fused q-projection + attention -> g_o       [256 x 512] flat
    qattn_kernel<<<dim3(HH, BB), 256>>>(in_w, in_b);

    // out_proj split-K partials, then fused (sum + bias + residual + LN)
    gemm_splitk<<<dim3(EE / 64, (BB * TT) / 64, 4), 256>>>(po, out_w, ppart);
    epi_ln<<<BB * TT, 128>>>(out_b, ln_g, ln_b);

    // FFN split-K partials, then fused (sum + bias + GELU + residual)
    gemm_splitk<<<dim3(EE / 64, (BB * TT) / 64, 4), 256>>>(pz, ffn_w, ppart);
    epi_ffn<<<BB * TT, 128>>>(ffn_b, out);
}

// round 7
// speedup vs baseline: 2.1562x; 1.2537x over previous
#include <cuda_runtime.h>
#include <cstdint>
#include <math.h>

#define BB 16
#define NN 32768
#define DD 256
#define EE 512
#define HH 8
#define KK 512
#define TT 16
#define NC 4      // attention key chunks
#define CK 128    // keys per chunk

// ---------------- device scratch (no allocations allowed) ----------------
__device__ float g_x[BB * KK * EE];          // projected x     16 MB
__device__ float g_kv[BB * KK * 2 * EE];     // k|v concat      32 MB
__device__ float g_q[BB * TT * EE];          // scaled q (256 x 512)
__device__ float g_o[BB * TT * EE];          // attn out (256 x 512 flat)
__device__ float g_z[BB * TT * EE];          // post layernorm
__device__ float g_part[4 * BB * TT * EE];   // split-K / attn partials (2 MB)
__device__ float g_m[NC * BB * HH * TT];     // chunk softmax max
__device__ float g_l[NC * BB * HH * TT];     // chunk softmax expsum
__device__ int   g_idx[BB * KK];             // top-k indices

// order-preserving float->uint key (bigger key == bigger float)
__device__ __forceinline__ unsigned fkey(float f) {
    unsigned u = __float_as_uint(f);
    return (u & 0x80000000u) ? ~u : (u | 0x80000000u);
}

// ---------------- top-K: smem-resident keys, radix select + bitonic sort ----
extern __shared__ unsigned skeys[];   // NN unsigned = 128 KB dynamic smem

__global__ void __launch_bounds__(1024) topk_kernel(const float* __restrict__ scores) {
    const int b = blockIdx.x;
    const float* s = scores + (size_t)b * NN;
    const int tid = threadIdx.x;  // 1024 threads

    __shared__ unsigned hist[256];
    __shared__ unsigned sh_prefix, sh_mask, sh_remk;
    __shared__ int sh_cntgt, sh_cnteq;
    __shared__ unsigned long long sel[512];
    __shared__ int eq[1024];

    if (tid == 0) { sh_prefix = 0u; sh_mask = 0u; sh_remk = KK; }
    if (tid < 256) hist[tid] = 0u;
    __syncthreads();

    for (int i = tid; i < NN; i += 1024) {
        unsigned k = fkey(__ldg(&s[i]));
        skeys[i] = k;
        atomicAdd(&hist[k >> 24], 1u);
    }
    __syncthreads();

    for (int pass = 0; pass < 4; pass++) {
        const int shift = 24 - pass * 8;
        if (tid == 0) {
            unsigned remk = sh_remk, acc = 0u;
            int d;
            for (d = 255; d >= 0; d--) {
                if (acc + hist[d] >= remk) break;
                acc += hist[d];
            }
            sh_remk  = remk - acc;
            sh_prefix = sh_prefix | ((unsigned)d << shift);
            sh_mask   = sh_mask | (0xFFu << shift);
            sh_cntgt = 0; sh_cnteq = 0;
        }
        __syncthreads();
        if (pass == 3) break;
        if (tid < 256) hist[tid] = 0u;
        __syncthreads();
        const unsigned prefix = sh_prefix, mask = sh_mask;
        const int nshift = shift - 8;
        for (int i = tid; i < NN; i += 1024) {
            unsigned k = skeys[i];
            if ((k & mask) == prefix) atomicAdd(&hist[(k >> nshift) & 255u], 1u);
        }
        __syncthreads();
    }

    const unsigned Tkey = sh_prefix;
    const int remk = (int)sh_remk;

    for (int i = tid; i < NN; i += 1024) {
        unsigned k = skeys[i];
        if (k > Tkey) {
            int p = atomicAdd(&sh_cntgt, 1);
            sel[p] = ((unsigned long long)k << 32) | (unsigned)(0xFFFFFFFFu - (unsigned)i);
        } else if (k == Tkey) {
            int p = atomicAdd(&sh_cnteq, 1);
            if (p < 1024) eq[p] = i;
        }
    }
    __syncthreads();
    const int cntgt = sh_cntgt;
    const int cnteq = min(sh_cnteq, 1024);

    if (tid >= cnteq) eq[tid] = 0x7FFFFFFF;
    __syncthreads();
    for (unsigned k = 2; k <= 1024; k <<= 1)
        for (unsigned j = k >> 1; j > 0; j >>= 1) {
            unsigned i = tid, ixj = i ^ j;
            if (ixj > i) {
                int a = eq[i], c = eq[ixj];
                bool up = ((i & k) == 0);
                if ((a > c) == up) { eq[i] = c; eq[ixj] = a; }
            }
            __syncthreads();
        }
    for (int jj = tid; jj < remk; jj += 1024)
        sel[cntgt + jj] = ((unsigned long long)Tkey << 32) |
                          (unsigned)(0xFFFFFFFFu - (unsigned)eq[jj]);
    __syncthreads();

    for (unsigned k = 2; k <= 512; k <<= 1)
        for (unsigned j = k >> 1; j > 0; j >>= 1) {
            if (tid < 512) {
                unsigned i = tid, ixj = i ^ j;
                if (ixj > i) {
                    unsigned long long a = sel[i], c = sel[ixj];
                    bool up = ((i & k) == 0);
                    if ((a > c) == up) { sel[i] = c; sel[ixj] = a; }
                }
            }
            __syncthreads();
        }
    if (tid < 512)
        g_idx[b * KK + tid] =
            (int)(0xFFFFFFFFu - (unsigned)(sel[511 - tid] & 0xFFFFFFFFull));
}

// ====================== big-tile GEMM: C = A @ W^T + bias =================
#define LDP 132

#define G128_STS(BUF)                                                     \
    {                                                                     \
        float* as = As[BUF]; float* bs = Bs[BUF];                         \
        as[(lc + 0) * LDP + lr]      = ag0.x;                             \
        as[(lc + 1) * LDP + lr]      = ag0.y;                             \
        as[(lc + 2) * LDP + lr]      = ag0.z;                             \
        as[(lc + 3) * LDP + lr]      = ag0.w;                             \
        as[(lc + 0) * LDP + lr + 64] = ag1.x;                             \
        as[(lc + 1) * LDP + lr + 64] = ag1.y;                             \
        as[(lc + 2) * LDP + lr + 64] = ag1.z;                             \
        as[(lc + 3) * LDP + lr + 64] = ag1.w;                             \
        bs[(lc + 0) * LDP + lr]      = bg0.x;                             \
        bs[(lc + 1) * LDP + lr]      = bg0.y;                             \
        bs[(lc + 2) * LDP + lr]      = bg0.z;                             \
        bs[(lc + 3) * LDP + lr]      = bg0.w;                             \
        bs[(lc + 0) * LDP + lr + 64] = bg1.x;                             \
        bs[(lc + 1) * LDP + lr + 64] = bg1.y;                             \
        bs[(lc + 2) * LDP + lr + 64] = bg1.z;                             \
        bs[(lc + 3) * LDP + lr + 64] = bg1.w;                             \
    }

#define G128_COMPUTE(BUF)                                                 \
    _Pragma("unroll")                                                     \
    for (int k = 0; k < 16; k++) {                                        \
        float a[8], bb[8];                                                \
        *(float4*)&a[0]  = *(const float4*)&As[BUF][k * LDP + ty4];       \
        *(float4*)&a[4]  = *(const float4*)&As[BUF][k * LDP + 64 + ty4];  \
        *(float4*)&bb[0] = *(const float4*)&Bs[BUF][k * LDP + tx4];       \
        *(float4*)&bb[4] = *(const float4*)&Bs[BUF][k * LDP + 64 + tx4];  \
        _Pragma("unroll")                                                 \
        for (int i = 0; i < 8; i++)                                       \
            _Pragma("unroll")                                             \
            for (int j = 0; j < 8; j++)                                   \
                acc[i][j] = fmaf(a[i], bb[j], acc[i][j]);                 \
    }

__global__ void __launch_bounds__(256, 2)
gemm128(const float* __restrict__ A, long long strideA,
        const float* __restrict__ W,
        const float* __restrict__ bias,
        float* __restrict__ C, long long strideC,
        int Kd,
        const int* __restrict__ idxp, const float* __restrict__ gfeat) {
    const int b = blockIdx.z;
    float* Cb = C + (long long)b * strideC;
    const int N = gridDim.x * 128;

    __shared__ __align__(16) float As[2][16 * LDP];
    __shared__ __align__(16) float Bs[2][16 * LDP];

    const int tid = threadIdx.x;
    const int tx4 = (tid & 15) * 4, ty4 = (tid >> 4) * 4;
    const int row0 = blockIdx.y * 128, col0 = blockIdx.x * 128;
    const int lr = tid >> 2;
    const int lc = (tid & 3) << 2;

    const float* Ar0;
    const float* Ar1;
    if (idxp) {
        const int* ib = idxp + b * KK;
        Ar0 = gfeat + ((size_t)b * NN + ib[row0 + lr]) * Kd + lc;
        Ar1 = gfeat + ((size_t)b * NN + ib[row0 + lr + 64]) * Kd + lc;
    } else {
        const float* Ab = A + (long long)b * strideA;
        Ar0 = Ab + (long long)(row0 + lr) * Kd + lc;
        Ar1 = Ab + (long long)(row0 + lr + 64) * Kd + lc;
    }
    const float* Wr0 = W + (long long)(col0 + lr) * Kd + lc;
    const float* Wr1 = W + (long long)(col0 + lr + 64) * Kd + lc;

    float acc[8][8];
#pragma unroll
    for (int i = 0; i < 8; i++)
#pragma unroll
        for (int j = 0; j < 8; j++) acc[i][j] = 0.f;

    float4 ag0 = *(const float4*)(Ar0);
    float4 ag1 = *(const float4*)(Ar1);
    float4 bg0 = *(const float4*)(Wr0);
    float4 bg1 = *(const float4*)(Wr1);
    G128_STS(0)
    __syncthreads();

    int buf = 0;
    for (int k0 = 16; k0 < Kd; k0 += 16) {
        ag0 = *(const float4*)(Ar0 + k0);
        ag1 = *(const float4*)(Ar1 + k0);
        bg0 = *(const float4*)(Wr0 + k0);
        bg1 = *(const float4*)(Wr1 + k0);
        G128_COMPUTE(buf)
        G128_STS(buf ^ 1)
        __syncthreads();
        buf ^= 1;
    }
    G128_COMPUTE(buf)

#pragma unroll
    for (int i = 0; i < 8; i++) {
        int m = row0 + ty4 + (i & 3) + ((i >= 4) ? 64 : 0);
        float4 v0, v1;
        v0.x = acc[i][0] + bias[col0 + tx4 + 0];
        v0.y = acc[i][1] + bias[col0 + tx4 + 1];
        v0.z = acc[i][2] + bias[col0 + tx4 + 2];
        v0.w = acc[i][3] + bias[col0 + tx4 + 3];
        v1.x = acc[i][4] + bias[col0 + 64 + tx4 + 0];
        v1.y = acc[i][5] + bias[col0 + 64 + tx4 + 1];
        v1.z = acc[i][6] + bias[col0 + 64 + tx4 + 2];
        v1.w = acc[i][7] + bias[col0 + 64 + tx4 + 3];
        *(float4*)(Cb + (long long)m * N + col0 + tx4)      = v0;
        *(float4*)(Cb + (long long)m * N + col0 + 64 + tx4) = v1;
    }
}

// ============ split-K GEMM partials: part[kc] = A @ W^T (chunk kc) =========
#define SKP 68

#define SK_STS(BUF)                                                       \
    {                                                                     \
        float* as = As[BUF]; float* bs = Bs[BUF];                         \
        as[(lc + 0) * SKP + lr] = av.x;                                   \
        as[(lc + 1) * SKP + lr] = av.y;                                   \
        as[(lc + 2) * SKP + lr] = av.z;                                   \
        as[(lc + 3) * SKP + lr] = av.w;                                   \
        bs[(lc + 0) * SKP + lr] = bv.x;                                   \
        bs[(lc + 1) * SKP + lr] = bv.y;                                   \
        bs[(lc + 2) * SKP + lr] = bv.z;                                   \
        bs[(lc + 3) * SKP + lr] = bv.w;                                   \
    }

#define SK_COMPUTE(BUF)                                                   \
    _Pragma("unroll")                                                     \
    for (int k = 0; k < 16; k++) {                                        \
        float a[4], bb[4];                                                \
        *(float4*)a  = *(const float4*)&As[BUF][k * SKP + ty4];           \
        *(float4*)bb = *(const float4*)&Bs[BUF][k * SKP + tx4];           \
        _Pragma("unroll")                                                 \
        for (int i = 0; i < 4; i++)                                       \
            _Pragma("unroll")                                             \
            for (int j = 0; j < 4; j++)                                   \
                acc[i][j] = fmaf(a[i], bb[j], acc[i][j]);                 \
    }

__global__ void __launch_bounds__(256)
gemm_splitk(const float* __restrict__ A, const float* __restrict__ W,
            float* __restrict__ part) {
    const int kc = blockIdx.z;
    const int row0 = blockIdx.y * 64, col0 = blockIdx.x * 64;
    const int tid = threadIdx.x;
    const int tx4 = (tid & 15) * 4, ty4 = (tid >> 4) * 4;
    const int lr = tid >> 2, lc = (tid & 3) << 2;

    __shared__ __align__(16) float As[2][16 * SKP];
    __shared__ __align__(16) float Bs[2][16 * SKP];

    const float* Ar = A + (size_t)(row0 + lr) * EE + kc * 128 + lc;
    const float* Wr = W + (size_t)(col0 + lr) * EE + kc * 128 + lc;

    float acc[4][4];
#pragma unroll
    for (int i = 0; i < 4; i++)
#pragma unroll
        for (int j = 0; j < 4; j++) acc[i][j] = 0.f;

    float4 av = *(const float4*)(Ar);
    float4 bv = *(const float4*)(Wr);
    SK_STS(0)
    __syncthreads();

    int buf = 0;
#pragma unroll
    for (int k0 = 16; k0 < 128; k0 += 16) {
        av = *(const float4*)(Ar + k0);
        bv = *(const float4*)(Wr + k0);
        SK_COMPUTE(buf)
        SK_STS(buf ^ 1)
        __syncthreads();
        buf ^= 1;
    }
    SK_COMPUTE(buf)

    float* pp = part + (size_t)kc * (BB * TT * EE);
#pragma unroll
    for (int i = 0; i < 4; i++) {
        float4 v;
        v.x = acc[i][0]; v.y = acc[i][1]; v.z = acc[i][2]; v.w = acc[i][3];
        *(float4*)(pp + (size_t)(row0 + ty4 + i) * EE + col0 + tx4) = v;
    }
}

// ---------------- q projection: g_q = (x[:, :16] @ Wq^T + bq) / 8 ----------
__global__ void __launch_bounds__(256)
qproj_kernel(const float* __restrict__ Wq, const float* __restrict__ bq) {
    const int h = blockIdx.x, b = blockIdx.y;
    __shared__ float xs[TT][EE];
    const int tid = threadIdx.x;  // 256

    {
        const float4* xb4 = (const float4*)(g_x + (size_t)b * KK * EE);
        float4* b4 = (float4*)xs;
        for (int i = tid; i < TT * EE / 4; i += 256) b4[i] = xb4[i];
    }
    __syncthreads();

    const int d = tid & 63, tg = tid >> 6;
    const float4* wrow = (const float4*)(Wq + (size_t)(h * 64 + d) * EE);
    float acc[4] = {0.f, 0.f, 0.f, 0.f};
    for (int e4 = 0; e4 < EE / 4; e4++) {
        float4 w = wrow[e4];
#pragma unroll
        for (int i = 0; i < 4; i++) {
            const float* xr = &xs[tg + i * 4][e4 * 4];
            acc[i] += xr[0] * w.x + xr[1] * w.y + xr[2] * w.z + xr[3] * w.w;
        }
    }
    const float bias = bq[h * 64 + d];
#pragma unroll
    for (int i = 0; i < 4; i++)
        g_q[((size_t)b * TT + tg + i * 4) * EE + h * 64 + d] =
            (acc[i] + bias) * 0.125f;
}

// -------- attention chunk: partial softmax numerator over 128 keys ---------
__global__ void __launch_bounds__(256)
attn_chunk() {
    const int h = blockIdx.x, b = blockIdx.y, c = blockIdx.z;
    const float* kb = g_kv + (size_t)b * KK * 2 * EE + h * 64;
    const float* vb = kb + EE;

    __shared__ float qs[TT][64];
    __shared__ float ks[CK * 65];       // stride 65: conflict-free per-key reads
    __shared__ float lg[TT][CK];
    __shared__ float vs[32][68];
    const int tid = threadIdx.x;  // 256

    // load q (pre-scaled): 1024 floats, coalesced float4
    {
        int t = tid >> 4;
        int d = (tid * 4) & 63;
        *(float4*)&qs[t][d] =
            *(const float4*)(g_q + ((size_t)b * TT + t) * EE + h * 64 + d);
    }
    // stage K chunk (coalesced rows: 16 threads x float4 per row)
    const int vr = tid >> 4, vc = (tid & 15) * 4;
    for (int r0 = 0; r0 < CK; r0 += 16) {
        float4 k4 = *(const float4*)(kb + (size_t)(c * CK + r0 + vr) * (2 * EE) + vc);
        float* kp = &ks[(r0 + vr) * 65 + vc];
        kp[0] = k4.x; kp[1] = k4.y; kp[2] = k4.z; kp[3] = k4.w;
    }
    __syncthreads();

    // logits: thread owns key kk for 8 queries
    {
        const int kk = tid & 127, th = tid >> 7;
        float acc[8];
#pragma unroll
        for (int i = 0; i < 8; i++) acc[i] = 0.f;
        const float* kr = &ks[kk * 65];
#pragma unroll 8
        for (int d = 0; d < 64; d++) {
            float kv = kr[d];
#pragma unroll
            for (int i = 0; i < 8; i++)
                acc[i] = fmaf(qs[th * 8 + i][d], kv, acc[i]);
        }
#pragma unroll
        for (int i = 0; i < 8; i++) lg[th * 8 + i][kk] = acc[i];
    }
    __syncthreads();

    // per-chunk softmax stats + numerator (8 warps x 2 rows)
    const int w = tid >> 5, lane = tid & 31;
    for (int t = w; t < TT; t += 8) {
        float m = -1e30f;
        for (int i = lane; i < CK; i += 32) m = fmaxf(m, lg[t][i]);
#pragma unroll
        for (int o = 16; o > 0; o >>= 1) m = fmaxf(m, __shfl_xor_sync(0xFFFFFFFFu, m, o));
        float ssum = 0.f;
        for (int i = lane; i < CK; i += 32) {
            float e = __expf(lg[t][i] - m);
            lg[t][i] = e; ssum += e;
        }
#pragma unroll
        for (int o = 16; o > 0; o >>= 1) ssum += __shfl_xor_sync(0xFFFFFFFFu, ssum, o);
        if (lane == 0) {
            g_m[((size_t)(c * BB + b) * HH + h) * TT + t] = m;
            g_l[((size_t)(c * BB + b) * HH + h) * TT + t] = ssum;
        }
    }

    // partial O = e @ V over this chunk via 32-row V tiles
    const int d = tid & 63, tg = tid >> 6;
    float acc4[4] = {0.f, 0.f, 0.f, 0.f};
    for (int kk0 = 0; kk0 < CK; kk0 += 32) {
        __syncthreads();
        const float* vrow = vb + (size_t)(c * CK + kk0 + vr) * (2 * EE) + vc;
        float4 v0 = *(const float4*)(vrow);
        float4 v1 = *(const float4*)(vrow + (size_t)16 * 2 * EE);
        *(float4*)&vs[vr][vc]      = v0;
        *(float4*)&vs[vr + 16][vc] = v1;
        __syncthreads();
#pragma unroll
        for (int r = 0; r < 32; r++) {
            float v = vs[r][d];
#pragma unroll
            for (int i = 0; i < 4; i++)
                acc4[i] = fmaf(lg[tg + i * 4][kk0 + r], v, acc4[i]);
        }
    }
#pragma unroll
    for (int i = 0; i < 4; i++)
        g_part[((size_t)(c * BB + b) * TT + tg + i * 4) * EE + h * 64 + d] = acc4[i];
}

// -------- attention combine: merge 4 chunks (log-sum-exp) -> g_o ----------
__global__ void __launch_bounds__(256)
attn_combine() {
    const int h = blockIdx.x, b = blockIdx.y;
    const int tid = threadIdx.x;
    const int d = tid & 63, tg = tid >> 6;
#pragma unroll
    for (int i = 0; i < 4; i++) {
        const int t = tg + i * 4;
        float m[NC], l[NC];
#pragma unroll
        for (int c = 0; c < NC; c++) {
            m[c] = g_m[((size_t)(c * BB + b) * HH + h) * TT + t];
            l[c] = g_l[((size_t)(c * BB + b) * HH + h) * TT + t];
        }
        float mstar = fmaxf(fmaxf(m[0], m[1]), fmaxf(m[2], m[3]));
        float wgt[NC], denom = 0.f;
#pragma unroll
        for (int c = 0; c < NC; c++) {
            wgt[c] = __expf(m[c] - mstar);
            denom += wgt[c] * l[c];
        }
        float o = 0.f;
#pragma unroll
        for (int c = 0; c < NC; c++)
            o += wgt[c] *
                 g_part[((size_t)(c * BB + b) * TT + t) * EE + h * 64 + d];
        g_o[((size_t)b * TT + t) * EE + h * 64 + d] = o / denom;
    }
}

// -------- epilogue 1: y = sum(part) + bo + x_res ; z = LN(y) --------------
__global__ void __launch_bounds__(128)
epi_ln(const float* __restrict__ bo,
       const float* __restrict__ lng, const float* __restrict__ lnb) {
    const int row = blockIdx.x;   // 0..255
    const int tid = threadIdx.x;  // 128
    const float* xres = g_x + ((size_t)(row >> 4) * KK + (row & 15)) * EE;
    float* zr = g_z + (size_t)row * EE;
    __shared__ float red[4];

    float v[4];
#pragma unroll
    for (int u = 0; u < 4; u++) {
        int e = tid + u * 128;
        size_t o = (size_t)row * EE + e;
        float s = g_part[o] + g_part[o + 1 * BB * TT * EE] +
                  g_part[o + 2 * BB * TT * EE] + g_part[o + 3 * BB * TT * EE];
        v[u] = s + bo[e] + xres[e];
    }

    float s = v[0] + v[1] + v[2] + v[3];
#pragma unroll
    for (int o = 16; o > 0; o >>= 1) s += __shfl_xor_sync(0xFFFFFFFFu, s, o);
    if ((tid & 31) == 0) red[tid >> 5] = s;
    __syncthreads();
    const float mu = (red[0] + red[1] + red[2] + red[3]) / EE;
    __syncthreads();

    float q = 0.f;
#pragma unroll
    for (int u = 0; u < 4; u++) { float dlt = v[u] - mu; q += dlt * dlt; }
#pragma unroll
    for (int o = 16; o > 0; o >>= 1) q += __shfl_xor_sync(0xFFFFFFFFu, q, o);
    if ((tid & 31) == 0) red[tid >> 5] = q;
    __syncthreads();
    const float rstd = rsqrtf((red[0] + red[1] + red[2] + red[3]) / EE + 1e-5f);

#pragma unroll
    for (int u = 0; u < 4; u++) {
        int e = tid + u * 128;
        zr[e] = (v[u] - mu) * rstd * lng[e] + lnb[e];
    }
}

// -------- epilogue 2: out = z + gelu(sum(part) + bf) ----------------------
__global__ void __launch_bounds__(128)
epi_ffn(const float* __restrict__ bf, float* __restrict__ out) {
    const int row = blockIdx.x;
    const int tid = threadIdx.x;
    const float* zr = g_z + (size_t)row * EE;
    float* outp = out + (size_t)row * EE;
#pragma unroll
    for (int u = 0; u < 4; u++) {
        int e = tid + u * 128;
        size_t o = (size_t)row * EE + e;
        float t = g_part[o] + g_part[o + 1 * BB * TT * EE] +
                  g_part[o + 2 * BB * TT * EE] + g_part[o + 3 * BB * TT * EE] +
                  bf[e];
        float g = 0.5f * t * (1.f + erff(t * 0.70710678118654752f));
        outp[e] = zr[e] + g;
    }
}

// ---------------- launch ----------------
extern "C" void kernel_launch(void* const* d_in, const int* in_sizes, int n_in,
                              void* d_out, int out_size) {
    (void)in_sizes; (void)n_in; (void)out_size;
    const float* feats  = (const float*)d_in[0];
    const float* scores = (const float*)d_in[1];
    const float* proj_w = (const float*)d_in[2];
    const float* proj_b = (const float*)d_in[3];
    const float* in_w   = (const float*)d_in[4];
    const float* in_b   = (const float*)d_in[5];
    const float* out_w  = (const float*)d_in[6];
    const float* out_b  = (const float*)d_in[7];
    const float* ln_g   = (const float*)d_in[8];
    const float* ln_b   = (const float*)d_in[9];
    const float* ffn_w  = (const float*)d_in[10];
    const float* ffn_b  = (const float*)d_in[11];
    float* out = (float*)d_out;

    float *px, *pkv, *po, *pz, *ppart;
    int* pidx;
    cudaGetSymbolAddress((void**)&px,    g_x);
    cudaGetSymbolAddress((void**)&pkv,   g_kv);
    cudaGetSymbolAddress((void**)&po,    g_o);
    cudaGetSymbolAddress((void**)&pz,    g_z);
    cudaGetSymbolAddress((void**)&ppart, g_part);
    cudaGetSymbolAddress((void**)&pidx,  g_idx);

    static int smem_set = 0;
    if (!smem_set) {
        cudaFuncSetAttribute(topk_kernel,
                             cudaFuncAttributeMaxDynamicSharedMemorySize,
                             NN * (int)sizeof(unsigned));
        smem_set = 1;
    }

    topk_kernel<<<BB, 1024, NN * sizeof(unsigned)>>>(scores);

    // x = feats[idx] @ proj_w^T + proj_b          [512 x 512] per batch (fused gather)
    gemm128<<<dim3(EE / 128, KK / 128, BB), 256>>>(
        nullptr, 0LL, proj_w, proj_b, px, (long long)KK * EE, DD, pidx, feats);
    // kv = x @ [Wk;Wv]^T + b                      [512 x 1024] per batch
    gemm128<<<dim3(2 * EE / 128, KK / 128, BB), 256>>>(
        px, (long long)KK * EE, in_w + EE * EE, in_b + EE, pkv,
        (long long)KK * 2 * EE, EE, nullptr, nullptr);

    // attention: q proj, chunked flash partials, combine
    qproj_kernel<<<dim3(HH, BB), 256>>>(in_w, in_b);
    attn_chunk<<<dim3(HH, BB, NC), 256>>>();
    attn_combine<<<dim3(HH, BB), 256>>>();

    // out_proj split-K partials, then fused (sum + bias + residual + LN)
    gemm_splitk<<<dim3(EE / 64, (BB * TT) / 64, 4), 256>>>(po, out_w, ppart);
    epi_ln<<<BB * TT, 128>>>(out_b, ln_g, ln_b);

    // FFN split-K partials, then fused (sum + bias + GELU + residual)
    gemm_splitk<<<dim3(EE / 64, (BB * TT) / 64, 4), 256>>>(pz, ffn_w, ppart);
    epi_ffn<<<BB * TT, 128>>>(ffn_b, out);
}

// round 9
// speedup vs baseline: 2.9884x; 1.3859x over previous
#include <cuda_runtime.h>
#include <cuda_bf16.h>
#include <cstdint>
#include <math.h>

#define BB 16
#define NN 32768
#define DD 256
#define EE 512
#define HH 8
#define KK 512
#define TT 16
#define NC 4      // attention key chunks
#define CK 128    // keys per chunk

typedef __nv_bfloat16 bf16;

// ---------------- device scratch (no allocations allowed) ----------------
__device__ float g_x[BB * KK * EE];          // projected x fp32 (residual source)
__device__ bf16  g_xh[BB * KK * EE];         // x hi (bf16)
__device__ bf16  g_xl[BB * KK * EE];         // x lo (bf16)
__device__ bf16  g_fh[BB * KK * DD];         // gathered feats hi
__device__ bf16  g_fl[BB * KK * DD];         // gathered feats lo
__device__ bf16  g_wph[EE * DD];             // proj_w hi/lo
__device__ bf16  g_wpl[EE * DD];
__device__ bf16  g_wkh[2 * EE * EE];         // kv weight hi/lo
__device__ bf16  g_wkl[2 * EE * EE];
__device__ float g_kv[BB * KK * 2 * EE];     // k|v concat fp32
__device__ float g_q[BB * TT * EE];          // scaled q
__device__ float g_o[BB * TT * EE];          // attn out
__device__ float g_z[BB * TT * EE];          // post layernorm
__device__ float g_part[4 * BB * TT * EE];   // split-K / attn partials
__device__ float g_m[NC * BB * HH * TT];
__device__ float g_l[NC * BB * HH * TT];
__device__ int   g_idx[BB * KK];

// order-preserving float->uint key (bigger key == bigger float)
__device__ __forceinline__ unsigned fkey(float f) {
    unsigned u = __float_as_uint(f);
    return (u & 0x80000000u) ? ~u : (u | 0x80000000u);
}

__device__ __forceinline__ void split_bf16(float f, bf16& h, bf16& l) {
    h = __float2bfloat16(f);
    l = __float2bfloat16(f - __bfloat162float(h));
}

// ---------------- top-K: smem-resident keys, radix select + bitonic sort ----
extern __shared__ unsigned skeys[];   // NN unsigned = 128 KB dynamic smem

__global__ void __launch_bounds__(1024) topk_kernel(const float* __restrict__ scores) {
    const int b = blockIdx.x;
    const float* s = scores + (size_t)b * NN;
    const int tid = threadIdx.x;

    __shared__ unsigned hist[256];
    __shared__ unsigned sh_prefix, sh_mask, sh_remk;
    __shared__ int sh_cntgt, sh_cnteq;
    __shared__ unsigned long long sel[512];
    __shared__ int eq[1024];

    if (tid == 0) { sh_prefix = 0u; sh_mask = 0u; sh_remk = KK; }
    if (tid < 256) hist[tid] = 0u;
    __syncthreads();

    for (int i = tid; i < NN; i += 1024) {
        unsigned k = fkey(__ldg(&s[i]));
        skeys[i] = k;
        atomicAdd(&hist[k >> 24], 1u);
    }
    __syncthreads();

    for (int pass = 0; pass < 4; pass++) {
        const int shift = 24 - pass * 8;
        if (tid == 0) {
            unsigned remk = sh_remk, acc = 0u;
            int d;
            for (d = 255; d >= 0; d--) {
                if (acc + hist[d] >= remk) break;
                acc += hist[d];
            }
            sh_remk  = remk - acc;
            sh_prefix = sh_prefix | ((unsigned)d << shift);
            sh_mask   = sh_mask | (0xFFu << shift);
            sh_cntgt = 0; sh_cnteq = 0;
        }
        __syncthreads();
        if (pass == 3) break;
        if (tid < 256) hist[tid] = 0u;
        __syncthreads();
        const unsigned prefix = sh_prefix, mask = sh_mask;
        const int nshift = shift - 8;
        for (int i = tid; i < NN; i += 1024) {
            unsigned k = skeys[i];
            if ((k & mask) == prefix) atomicAdd(&hist[(k >> nshift) & 255u], 1u);
        }
        __syncthreads();
    }

    const unsigned Tkey = sh_prefix;
    const int remk = (int)sh_remk;

    for (int i = tid; i < NN; i += 1024) {
        unsigned k = skeys[i];
        if (k > Tkey) {
            int p = atomicAdd(&sh_cntgt, 1);
            sel[p] = ((unsigned long long)k << 32) | (unsigned)(0xFFFFFFFFu - (unsigned)i);
        } else if (k == Tkey) {
            int p = atomicAdd(&sh_cnteq, 1);
            if (p < 1024) eq[p] = i;
        }
    }
    __syncthreads();
    const int cntgt = sh_cntgt;
    const int cnteq = min(sh_cnteq, 1024);

    if (tid >= cnteq) eq[tid] = 0x7FFFFFFF;
    __syncthreads();
    for (unsigned k = 2; k <= 1024; k <<= 1)
        for (unsigned j = k >> 1; j > 0; j >>= 1) {
            unsigned i = tid, ixj = i ^ j;
            if (ixj > i) {
                int a = eq[i], c = eq[ixj];
                bool up = ((i & k) == 0);
                if ((a > c) == up) { eq[i] = c; eq[ixj] = a; }
            }
            __syncthreads();
        }
    for (int jj = tid; jj < remk; jj += 1024)
        sel[cntgt + jj] = ((unsigned long long)Tkey << 32) |
                          (unsigned)(0xFFFFFFFFu - (unsigned)eq[jj]);
    __syncthreads();

    for (unsigned k = 2; k <= 512; k <<= 1)
        for (unsigned j = k >> 1; j > 0; j >>= 1) {
            if (tid < 512) {
                unsigned i = tid, ixj = i ^ j;
                if (ixj > i) {
                    unsigned long long a = sel[i], c = sel[ixj];
                    bool up = ((i & k) == 0);
                    if ((a > c) == up) { sel[i] = c; sel[ixj] = a; }
                }
            }
            __syncthreads();
        }
    if (tid < 512)
        g_idx[b * KK + tid] =
            (int)(0xFFFFFFFFu - (unsigned)(sel[511 - tid] & 0xFFFFFFFFull));
}

// ---------------- conversions -------------------------------------------
// gather + split feats: row t of batch b <- feats[b, idx[b,t], :]
__global__ void __launch_bounds__(64)
conv_feats(const float* __restrict__ feats) {
    const int t = blockIdx.x, b = blockIdx.y;
    const int src = g_idx[b * KK + t];
    const float* sp = feats + ((size_t)b * NN + src) * DD;
    bf16* hp = g_fh + ((size_t)b * KK + t) * DD;
    bf16* lp = g_fl + ((size_t)b * KK + t) * DD;
#pragma unroll
    for (int u = 0; u < 4; u++) {
        int i = threadIdx.x + u * 64;
        bf16 h, l;
        split_bf16(sp[i], h, l);
        hp[i] = h; lp[i] = l;
    }
}

// split a weight matrix [R, C] fp32 -> h/l bf16
__global__ void __launch_bounds__(128)
conv_w(const float* __restrict__ W, bf16* __restrict__ Wh, bf16* __restrict__ Wl,
       int C) {
    const int r = blockIdx.x;
    for (int c = threadIdx.x; c < C; c += 128) {
        bf16 h, l;
        split_bf16(W[(size_t)r * C + c], h, l);
        Wh[(size_t)r * C + c] = h;
        Wl[(size_t)r * C + c] = l;
    }
}

// ============== tensor-core split-bf16 GEMM: C = A @ W^T + bias ============
// A (hi/lo bf16) [rows, Kd] row-major per batch, W (hi/lo) [N, Kd].
// CTA tile 128x64, warp tile 32x32, mma m16n8k16 x 3 products (hh, hl, lh).
// Optionally also writes bf16 hi/lo split of C (for feeding next GEMM).
#define AP 40          // smem pitch in bf16 (80B: conflict-free ldmatrix)
#define SA_ELEM (128 * AP)
#define SW_ELEM (64 * AP)
#define TC_SMEM ((2 * SA_ELEM * 2 + 2 * SW_ELEM * 2) * 2)  // bytes = 61440

__device__ __forceinline__ void ldsm4(uint32_t r[4], uint32_t addr) {
    asm volatile("ldmatrix.sync.aligned.m8n8.x4.shared.b16 {%0,%1,%2,%3}, [%4];"
                 : "=r"(r[0]), "=r"(r[1]), "=r"(r[2]), "=r"(r[3]) : "r"(addr));
}
__device__ __forceinline__ void mma_bf16(float c[4], const uint32_t a[4],
                                         uint32_t b0, uint32_t b1) {
    asm volatile(
        "mma.sync.aligned.m16n8k16.row.col.f32.bf16.bf16.f32 "
        "{%0,%1,%2,%3}, {%4,%5,%6,%7}, {%8,%9}, {%0,%1,%2,%3};"
        : "+f"(c[0]), "+f"(c[1]), "+f"(c[2]), "+f"(c[3])
        : "r"(a[0]), "r"(a[1]), "r"(a[2]), "r"(a[3]), "r"(b0), "r"(b1));
}

#define TC_STS(BUF)                                                       \
    {                                                                     \
        *(uint4*)&sAh[(BUF) * SA_ELEM + arow * AP + achk]        = pAh0;  \
        *(uint4*)&sAh[(BUF) * SA_ELEM + (arow + 64) * AP + achk] = pAh1;  \
        *(uint4*)&sAl[(BUF) * SA_ELEM + arow * AP + achk]        = pAl0;  \
        *(uint4*)&sAl[(BUF) * SA_ELEM + (arow + 64) * AP + achk] = pAl1;  \
        *(uint4*)&sWh[(BUF) * SW_ELEM + arow * AP + achk]        = pWh;   \
        *(uint4*)&sWl[(BUF) * SW_ELEM + arow * AP + achk]        = pWl;   \
    }

#define TC_COMPUTE(BUF)                                                   \
    _Pragma("unroll")                                                     \
    for (int ks = 0; ks < 32; ks += 16) {                                 \
        uint32_t ah[2][4], al[2][4], wh[2][4], wl[2][4];                  \
        _Pragma("unroll")                                                 \
        for (int mt = 0; mt < 2; mt++) {                                  \
            uint32_t off = 2u * ((BUF) * SA_ELEM + (wm + mt * 16) * AP + aoffA + ks); \
            ldsm4(ah[mt], baseAh + off);                                  \
            ldsm4(al[mt], baseAl + off);                                  \
        }                                                                 \
        _Pragma("unroll")                                                 \
        for (int np = 0; np < 2; np++) {                                  \
            uint32_t off = 2u * ((BUF) * SW_ELEM + (wn + np * 16) * AP + woffW + ks); \
            ldsm4(wh[np], baseWh + off);                                  \
            ldsm4(wl[np], baseWl + off);                                  \
        }                                                                 \
        _Pragma("unroll")                                                 \
        for (int mt = 0; mt < 2; mt++)                                    \
            _Pragma("unroll")                                             \
            for (int nt = 0; nt < 4; nt++) {                              \
                uint32_t bh0 = wh[nt >> 1][(nt & 1) * 2];                 \
                uint32_t bh1 = wh[nt >> 1][(nt & 1) * 2 + 1];             \
                uint32_t bl0 = wl[nt >> 1][(nt & 1) * 2];                 \
                uint32_t bl1 = wl[nt >> 1][(nt & 1) * 2 + 1];             \
                mma_bf16(acc[mt][nt], ah[mt], bh0, bh1);                  \
                mma_bf16(acc[mt][nt], ah[mt], bl0, bl1);                  \
                mma_bf16(acc[mt][nt], al[mt], bh0, bh1);                  \
            }                                                             \
    }

__global__ void __launch_bounds__(256, 2)
gemm_tc(const bf16* __restrict__ Ah, const bf16* __restrict__ Al,
        long long strideA,
        const bf16* __restrict__ Wh, const bf16* __restrict__ Wl,
        const float* __restrict__ bias,
        float* __restrict__ C, long long strideC,
        bf16* __restrict__ Ch, bf16* __restrict__ Cl,
        int Kd) {
    extern __shared__ __align__(16) char smraw[];
    bf16* sAh = (bf16*)smraw;
    bf16* sAl = sAh + 2 * SA_ELEM;
    bf16* sWh = sAl + 2 * SA_ELEM;
    bf16* sWl = sWh + 2 * SW_ELEM;

    const int b = blockIdx.z;
    const int row0 = blockIdx.y * 128, col0 = blockIdx.x * 64;
    const int N = gridDim.x * 64;
    const int tid = threadIdx.x;
    const int lane = tid & 31, wid = tid >> 5;
    const int wm = (wid & 3) * 32, wn = (wid >> 2) * 32;

    const uint32_t baseAh = (uint32_t)__cvta_generic_to_shared(sAh);
    const uint32_t baseAl = (uint32_t)__cvta_generic_to_shared(sAl);
    const uint32_t baseWh = (uint32_t)__cvta_generic_to_shared(sWh);
    const uint32_t baseWl = (uint32_t)__cvta_generic_to_shared(sWl);
    const uint32_t aoffA = (lane & 15) * AP + ((lane >> 4) << 3);
    const uint32_t woffW = ((lane & 7) + ((lane & 16) >> 1)) * AP + (lane & 8);

    // loaders: A 128 rows x 4 chunks (2/thread), W 64 rows x 4 chunks (1/thread)
    const int arow = tid >> 2;           // 0..63
    const int achk = (tid & 3) * 8;      // bf16 offset within 32-col chunk
    const long long Aoff = (long long)b * strideA;
    const bf16* gAh0 = Ah + Aoff + (size_t)(row0 + arow) * Kd + achk;
    const bf16* gAh1 = Ah + Aoff + (size_t)(row0 + arow + 64) * Kd + achk;
    const bf16* gAl0 = Al + Aoff + (size_t)(row0 + arow) * Kd + achk;
    const bf16* gAl1 = Al + Aoff + (size_t)(row0 + arow + 64) * Kd + achk;
    const bf16* gWh  = Wh + (size_t)(col0 + arow) * Kd + achk;
    const bf16* gWl  = Wl + (size_t)(col0 + arow) * Kd + achk;

    float acc[2][4][4];
#pragma unroll
    for (int mt = 0; mt < 2; mt++)
#pragma unroll
        for (int nt = 0; nt < 4; nt++)
#pragma unroll
            for (int i = 0; i < 4; i++) acc[mt][nt][i] = 0.f;

    uint4 pAh0 = *(const uint4*)(gAh0);
    uint4 pAh1 = *(const uint4*)(gAh1);
    uint4 pAl0 = *(const uint4*)(gAl0);
    uint4 pAl1 = *(const uint4*)(gAl1);
    uint4 pWh  = *(const uint4*)(gWh);
    uint4 pWl  = *(const uint4*)(gWl);
    TC_STS(0)
    __syncthreads();

    int buf = 0;
    for (int k0 = 32; k0 < Kd; k0 += 32) {
        pAh0 = *(const uint4*)(gAh0 + k0);
        pAh1 = *(const uint4*)(gAh1 + k0);
        pAl0 = *(const uint4*)(gAl0 + k0);
        pAl1 = *(const uint4*)(gAl1 + k0);
        pWh  = *(const uint4*)(gWh + k0);
        pWl  = *(const uint4*)(gWl + k0);
        TC_COMPUTE(buf)
        TC_STS(buf ^ 1)
        __syncthreads();
        buf ^= 1;
    }
    TC_COMPUTE(buf)

    // epilogue
    const int g = lane >> 2, tq = (lane & 3) * 2;
#pragma unroll
    for (int mt = 0; mt < 2; mt++)
#pragma unroll
        for (int nt = 0; nt < 4; nt++) {
            int r = row0 + wm + mt * 16 + g;
            int cc = col0 + wn + nt * 8 + tq;
            float b0 = bias[cc], b1 = bias[cc + 1];
            float v00 = acc[mt][nt][0] + b0, v01 = acc[mt][nt][1] + b1;
            float v10 = acc[mt][nt][2] + b0, v11 = acc[mt][nt][3] + b1;
            size_t i0 = (size_t)((long long)b * strideC) + (size_t)r * N + cc;
            size_t i1 = (size_t)((long long)b * strideC) + (size_t)(r + 8) * N + cc;
            *(float2*)(C + i0) = make_float2(v00, v01);
            *(float2*)(C + i1) = make_float2(v10, v11);
            if (Ch) {
                bf16 h, l;
                split_bf16(v00, h, l); Ch[i0] = h; Cl[i0] = l;
                split_bf16(v01, h, l); Ch[i0 + 1] = h; Cl[i0 + 1] = l;
                split_bf16(v10, h, l); Ch[i1] = h; Cl[i1] = l;
                split_bf16(v11, h, l); Ch[i1 + 1] = h; Cl[i1 + 1] = l;
            }
        }
}

// ============ split-K GEMM partials: part[kc] = A @ W^T (chunk kc) =========
// qmode: A row m -> ((m>>4)*KK + (m&15))  (first 16 rows of each batch of g_x)
#define SKP 68

#define SK_STS(BUF)                                                       \
    {                                                                     \
        float* as = As[BUF]; float* bs = Bs[BUF];                         \
        as[(lc + 0) * SKP + lr] = av.x;                                   \
        as[(lc + 1) * SKP + lr] = av.y;                                   \
        as[(lc + 2) * SKP + lr] = av.z;                                   \
        as[(lc + 3) * SKP + lr] = av.w;                                   \
        bs[(lc + 0) * SKP + lr] = bv.x;                                   \
        bs[(lc + 1) * SKP + lr] = bv.y;                                   \
        bs[(lc + 2) * SKP + lr] = bv.z;                                   \
        bs[(lc + 3) * SKP + lr] = bv.w;                                   \
    }

#define SK_COMPUTE(BUF)                                                   \
    _Pragma("unroll")                                                     \
    for (int k = 0; k < 16; k++) {                                        \
        float a[4], bb[4];                                                \
        *(float4*)a  = *(const float4*)&As[BUF][k * SKP + ty4];           \
        *(float4*)bb = *(const float4*)&Bs[BUF][k * SKP + tx4];           \
        _Pragma("unroll")                                                 \
        for (int i = 0; i < 4; i++)                                       \
            _Pragma("unroll")                                             \
            for (int j = 0; j < 4; j++)                                   \
                acc[i][j] = fmaf(a[i], bb[j], acc[i][j]);                 \
    }

__global__ void __launch_bounds__(256)
gemm_splitk(const float* __restrict__ A, const float* __restrict__ W,
            float* __restrict__ part, int qmode) {
    const int kc = blockIdx.z;
    const int row0 = blockIdx.y * 64, col0 = blockIdx.x * 64;
    const int tid = threadIdx.x;
    const int tx4 = (tid & 15) * 4, ty4 = (tid >> 4) * 4;
    const int lr = tid >> 2, lc = (tid & 3) << 2;

    __shared__ __align__(16) float As[2][16 * SKP];
    __shared__ __align__(16) float Bs[2][16 * SKP];

    long long arow = row0 + lr;
    if (qmode) arow = (arow >> 4) * KK + (arow & 15);
    const float* Ar = A + (size_t)arow * EE + kc * 128 + lc;
    const float* Wr = W + (size_t)(col0 + lr) * EE + kc * 128 + lc;

    float acc[4][4];
#pragma unroll
    for (int i = 0; i < 4; i++)
#pragma unroll
        for (int j = 0; j < 4; j++) acc[i][j] = 0.f;

    float4 av = *(const float4*)(Ar);
    float4 bv = *(const float4*)(Wr);
    SK_STS(0)
    __syncthreads();

    int buf = 0;
#pragma unroll
    for (int k0 = 16; k0 < 128; k0 += 16) {
        av = *(const float4*)(Ar + k0);
        bv = *(const float4*)(Wr + k0);
        SK_COMPUTE(buf)
        SK_STS(buf ^ 1)
        __syncthreads();
        buf ^= 1;
    }
    SK_COMPUTE(buf)

    float* pp = part + (size_t)kc * (BB * TT * EE);
#pragma unroll
    for (int i = 0; i < 4; i++) {
        float4 v;
        v.x = acc[i][0]; v.y = acc[i][1]; v.z = acc[i][2]; v.w = acc[i][3];
        *(float4*)(pp + (size_t)(row0 + ty4 + i) * EE + col0 + tx4) = v;
    }
}

// -------- epi_q: g_q = (sum(part) + bq) / 8 -------------------------------
__global__ void __launch_bounds__(128)
epi_q(const float* __restrict__ bq) {
    const int row = blockIdx.x;
    const int tid = threadIdx.x;
#pragma unroll
    for (int u = 0; u < 4; u++) {
        int e = tid + u * 128;
        size_t o = (size_t)row * EE + e;
        float t = g_part[o] + g_part[o + 1 * BB * TT * EE] +
                  g_part[o + 2 * BB * TT * EE] + g_part[o + 3 * BB * TT * EE];
        g_q[o] = (t + bq[e]) * 0.125f;
    }
}

// -------- attention chunk: partial softmax numerator over 128 keys ---------
__global__ void __launch_bounds__(256)
attn_chunk() {
    const int h = blockIdx.x, b = blockIdx.y, c = blockIdx.z;
    const float* kb = g_kv + (size_t)b * KK * 2 * EE + h * 64;
    const float* vb = kb + EE;

    __shared__ float qs[TT][64];
    __shared__ float ks[CK * 65];
    __shared__ float lg[TT][CK];
    __shared__ float vs[32][68];
    const int tid = threadIdx.x;

    {
        int t = tid >> 4;
        int d = (tid * 4) & 63;
        *(float4*)&qs[t][d] =
            *(const float4*)(g_q + ((size_t)b * TT + t) * EE + h * 64 + d);
    }
    const int vr = tid >> 4, vc = (tid & 15) * 4;
    for (int r0 = 0; r0 < CK; r0 += 16) {
        float4 k4 = *(const float4*)(kb + (size_t)(c * CK + r0 + vr) * (2 * EE) + vc);
        float* kp = &ks[(r0 + vr) * 65 + vc];
        kp[0] = k4.x; kp[1] = k4.y; kp[2] = k4.z; kp[3] = k4.w;
    }
    __syncthreads();

    {
        const int kk = tid & 127, th = tid >> 7;
        float acc[8];
#pragma unroll
        for (int i = 0; i < 8; i++) acc[i] = 0.f;
        const float* kr = &ks[kk * 65];
#pragma unroll 8
        for (int d = 0; d < 64; d++) {
            float kv = kr[d];
#pragma unroll
            for (int i = 0; i < 8; i++)
                acc[i] = fmaf(qs[th * 8 + i][d], kv, acc[i]);
        }
#pragma unroll
        for (int i = 0; i < 8; i++) lg[th * 8 + i][kk] = acc[i];
    }
    __syncthreads();

    const int w = tid >> 5, lane = tid & 31;
    for (int t = w; t < TT; t += 8) {
        float m = -1e30f;
        for (int i = lane; i < CK; i += 32) m = fmaxf(m, lg[t][i]);
#pragma unroll
        for (int o = 16; o > 0; o >>= 1) m = fmaxf(m, __shfl_xor_sync(0xFFFFFFFFu, m, o));
        float ssum = 0.f;
        for (int i = lane; i < CK; i += 32) {
            float e = __expf(lg[t][i] - m);
            lg[t][i] = e; ssum += e;
        }
#pragma unroll
        for (int o = 16; o > 0; o >>= 1) ssum += __shfl_xor_sync(0xFFFFFFFFu, ssum, o);
        if (lane == 0) {
            g_m[((size_t)(c * BB + b) * HH + h) * TT + t] = m;
            g_l[((size_t)(c * BB + b) * HH + h) * TT + t] = ssum;
        }
    }

    const int d = tid & 63, tg = tid >> 6;
    float acc4[4] = {0.f, 0.f, 0.f, 0.f};
    for (int kk0 = 0; kk0 < CK; kk0 += 32) {
        __syncthreads();
        const float* vrow = vb + (size_t)(c * CK + kk0 + vr) * (2 * EE) + vc;
        float4 v0 = *(const float4*)(vrow);
        float4 v1 = *(const float4*)(vrow + (size_t)16 * 2 * EE);
        *(float4*)&vs[vr][vc]      = v0;
        *(float4*)&vs[vr + 16][vc] = v1;
        __syncthreads();
#pragma unroll
        for (int r = 0; r < 32; r++) {
            float v = vs[r][d];
#pragma unroll
            for (int i = 0; i < 4; i++)
                acc4[i] = fmaf(lg[tg + i * 4][kk0 + r], v, acc4[i]);
        }
    }
#pragma unroll
    for (int i = 0; i < 4; i++)
        g_part[((size_t)(c * BB + b) * TT + tg + i * 4) * EE + h * 64 + d] = acc4[i];
}

// -------- attention combine: merge 4 chunks -> g_o ------------------------
__global__ void __launch_bounds__(256)
attn_combine() {
    const int h = blockIdx.x, b = blockIdx.y;
    const int tid = threadIdx.x;
    const int d = tid & 63, tg = tid >> 6;
#pragma unroll
    for (int i = 0; i < 4; i++) {
        const int t = tg + i * 4;
        float m[NC], l[NC];
#pragma unroll
        for (int c = 0; c < NC; c++) {
            m[c] = g_m[((size_t)(c * BB + b) * HH + h) * TT + t];
            l[c] = g_l[((size_t)(c * BB + b) * HH + h) * TT + t];
        }
        float mstar = fmaxf(fmaxf(m[0], m[1]), fmaxf(m[2], m[3]));
        float wgt[NC], denom = 0.f;
#pragma unroll
        for (int c = 0; c < NC; c++) {
            wgt[c] = __expf(m[c] - mstar);
            denom += wgt[c] * l[c];
        }
        float o = 0.f;
#pragma unroll
        for (int c = 0; c < NC; c++)
            o += wgt[c] *
                 g_part[((size_t)(c * BB + b) * TT + t) * EE + h * 64 + d];
        g_o[((size_t)b * TT + t) * EE + h * 64 + d] = o / denom;
    }
}

// -------- epilogue 1: y = sum(part) + bo + x_res ; z = LN(y) --------------
__global__ void __launch_bounds__(128)
epi_ln(const float* __restrict__ bo,
       const float* __restrict__ lng, const float* __restrict__ lnb) {
    const int row = blockIdx.x;
    const int tid = threadIdx.x;
    const float* xres = g_x + ((size_t)(row >> 4) * KK + (row & 15)) * EE;
    float* zr = g_z + (size_t)row * EE;
    __shared__ float red[4];

    float v[4];
#pragma unroll
    for (int u = 0; u < 4; u++) {
        int e = tid + u * 128;
        size_t o = (size_t)row * EE + e;
        float s = g_part[o] + g_part[o + 1 * BB * TT * EE] +
                  g_part[o + 2 * BB * TT * EE] + g_part[o + 3 * BB * TT * EE];
        v[u] = s + bo[e] + xres[e];
    }

    float s = v[0] + v[1] + v[2] + v[3];
#pragma unroll
    for (int o = 16; o > 0; o >>= 1) s += __shfl_xor_sync(0xFFFFFFFFu, s, o);
    if ((tid & 31) == 0) red[tid >> 5] = s;
    __syncthreads();
    const float mu = (red[0] + red[1] + red[2] + red[3]) / EE;
    __syncthreads();

    float q = 0.f;
#pragma unroll
    for (int u = 0; u < 4; u++) { float dlt = v[u] - mu; q += dlt * dlt; }
#pragma unroll
    for (int o = 16; o > 0; o >>= 1) q += __shfl_xor_sync(0xFFFFFFFFu, q, o);
    if ((tid & 31) == 0) red[tid >> 5] = q;
    __syncthreads();
    const float rstd = rsqrtf((red[0] + red[1] + red[2] + red[3]) / EE + 1e-5f);

#pragma unroll
    for (int u = 0; u < 4; u++) {
        int e = tid + u * 128;
        zr[e] = (v[u] - mu) * rstd * lng[e] + lnb[e];
    }
}

// -------- epilogue 2: out = z + gelu(sum(part) + bf) ----------------------
__global__ void __launch_bounds__(128)
epi_ffn(const float* __restrict__ bf, float* __restrict__ out) {
    const int row = blockIdx.x;
    const int tid = threadIdx.x;
    const float* zr = g_z + (size_t)row * EE;
    float* outp = out + (size_t)row * EE;
#pragma unroll
    for (int u = 0; u < 4; u++) {
        int e = tid + u * 128;
        size_t o = (size_t)row * EE + e;
        float t = g_part[o] + g_part[o + 1 * BB * TT * EE] +
                  g_part[o + 2 * BB * TT * EE] + g_part[o + 3 * BB * TT * EE] +
                  bf[e];
        float g = 0.5f * t * (1.f + erff(t * 0.70710678118654752f));
        outp[e] = zr[e] + g;
    }
}

// ---------------- launch ----------------
extern "C" void kernel_launch(void* const* d_in, const int* in_sizes, int n_in,
                              void* d_out, int out_size) {
    (void)in_sizes; (void)n_in; (void)out_size;
    const float* feats  = (const float*)d_in[0];
    const float* scores = (const float*)d_in[1];
    const float* proj_w = (const float*)d_in[2];
    const float* proj_b = (const float*)d_in[3];
    const float* in_w   = (const float*)d_in[4];
    const float* in_b   = (const float*)d_in[5];
    const float* out_w  = (const float*)d_in[6];
    const float* out_b  = (const float*)d_in[7];
    const float* ln_g   = (const float*)d_in[8];
    const float* ln_b   = (const float*)d_in[9];
    const float* ffn_w  = (const float*)d_in[10];
    const float* ffn_b  = (const float*)d_in[11];
    float* out = (float*)d_out;

    float *px, *pkv, *po, *pz, *ppart;
    bf16 *pxh, *pxl, *pfh, *pfl, *pwph, *pwpl, *pwkh, *pwkl;
    int* pidx;
    cudaGetSymbolAddress((void**)&px,    g_x);
    cudaGetSymbolAddress((void**)&pkv,   g_kv);
    cudaGetSymbolAddress((void**)&po,    g_o);
    cudaGetSymbolAddress((void**)&pz,    g_z);
    cudaGetSymbolAddress((void**)&ppart, g_part);
    cudaGetSymbolAddress((void**)&pidx,  g_idx);
    cudaGetSymbolAddress((void**)&pxh,   g_xh);
    cudaGetSymbolAddress((void**)&pxl,   g_xl);
    cudaGetSymbolAddress((void**)&pfh,   g_fh);
    cudaGetSymbolAddress((void**)&pfl,   g_fl);
    cudaGetSymbolAddress((void**)&pwph,  g_wph);
    cudaGetSymbolAddress((void**)&pwpl,  g_wpl);
    cudaGetSymbolAddress((void**)&pwkh,  g_wkh);
    cudaGetSymbolAddress((void**)&pwkl,  g_wkl);

    static int smem_set = 0;
    if (!smem_set) {
        cudaFuncSetAttribute(topk_kernel,
                             cudaFuncAttributeMaxDynamicSharedMemorySize,
                             NN * (int)sizeof(unsigned));
        cudaFuncSetAttribute(gemm_tc,
                             cudaFuncAttributeMaxDynamicSharedMemorySize,
                             TC_SMEM);
        smem_set = 1;
    }

    topk_kernel<<<BB, 1024, NN * sizeof(unsigned)>>>(scores);

    // conversions (weights + gathered feats) to bf16 hi/lo
    conv_feats<<<dim3(KK, BB), 64>>>(feats);
    conv_w<<<EE, 128>>>(proj_w, pwph, pwpl, DD);
    conv_w<<<2 * EE, 128>>>(in_w + EE * EE, pwkh, pwkl, EE);

    // x = feats[idx] @ proj_w^T + proj_b  (tensor-core split-bf16; also emits x h/l)
    gemm_tc<<<dim3(EE / 64, KK / 128, BB), 256, TC_SMEM>>>(
        pfh, pfl, (long long)KK * DD, pwph, pwpl, proj_b,
        px, (long long)KK * EE, pxh, pxl, DD);

    // kv = x @ [Wk;Wv]^T + b  (tensor-core split-bf16)
    gemm_tc<<<dim3(2 * EE / 64, KK / 128, BB), 256, TC_SMEM>>>(
        pxh, pxl, (long long)KK * EE, pwkh, pwkl, in_b + EE,
        pkv, (long long)KK * 2 * EE, nullptr, nullptr, EE);

    // q = (x[:, :16] @ Wq^T + bq)/8  via split-K + epilogue
    gemm_splitk<<<dim3(EE / 64, (BB * TT) / 64, 4), 256>>>(px, in_w, ppart, 1);
    epi_q<<<BB * TT, 128>>>(in_b);

    // attention: chunked flash partials, combine
    attn_chunk<<<dim3(HH, BB, NC), 256>>>();
    attn_combine<<<dim3(HH, BB), 256>>>();

    // out_proj split-K partials, then fused (sum + bias + residual + LN)
    gemm_splitk<<<dim3(EE / 64, (BB * TT) / 64, 4), 256>>>(po, out_w, ppart, 0);
    epi_ln<<<BB * TT, 128>>>(out_b, ln_g, ln_b);

    // FFN split-K partials, then fused (sum + bias + GELU + residual)
    gemm_splitk<<<dim3(EE / 64, (BB * TT) / 64, 4), 256>>>(pz, ffn_w, ppart, 0);
    epi_ffn<<<BB * TT, 128>>>(ffn_b, out);
}

// round 10
// speedup vs baseline: 3.5309x; 1.1815x over previous
#include <cuda_runtime.h>
#include <cuda_bf16.h>
#include <cstdint>
#include <math.h>

#define BB 16
#define NN 32768
#define DD 256
#define EE 512
#define HH 8
#define KK 512
#define TT 16
#define NC 4      // attention key chunks
#define CK 128    // keys per chunk

typedef __nv_bfloat16 bf16;

// ---------------- device scratch (no allocations allowed) ----------------
__device__ float g_x[BB * KK * EE];          // projected x fp32
__device__ bf16  g_wph[EE * DD];             // proj_w hi/lo
__device__ bf16  g_wpl[EE * DD];
__device__ bf16  g_wkh[2 * EE * EE];         // kv weight hi/lo
__device__ bf16  g_wkl[2 * EE * EE];
__device__ float g_kv[BB * KK * 2 * EE];     // k|v concat fp32
__device__ float g_q[BB * TT * EE];          // scaled q
__device__ float g_o[BB * TT * EE];          // attn out
__device__ float g_z[BB * TT * EE];          // post layernorm
__device__ float g_part[4 * BB * TT * EE];   // split-K / attn partials
__device__ float g_m[NC * BB * HH * TT];
__device__ float g_l[NC * BB * HH * TT];
__device__ int   g_idx[BB * KK];

// order-preserving float->uint key (bigger key == bigger float)
__device__ __forceinline__ unsigned fkey(float f) {
    unsigned u = __float_as_uint(f);
    return (u & 0x80000000u) ? ~u : (u | 0x80000000u);
}

__device__ __forceinline__ void split_bf16(float f, bf16& h, bf16& l) {
    h = __float2bfloat16(f);
    l = __float2bfloat16(f - __bfloat162float(h));
}

__device__ __forceinline__ uint32_t pk2(bf16 a, bf16 b) {
    return (uint32_t)__bfloat16_as_ushort(a) |
           ((uint32_t)__bfloat16_as_ushort(b) << 16);
}

// split 8 floats (two float4) into packed hi uint4 / lo uint4
__device__ __forceinline__ void pack8(float4 a, float4 b, uint4& h, uint4& l) {
    bf16 h0, l0, h1, l1;
    split_bf16(a.x, h0, l0); split_bf16(a.y, h1, l1);
    h.x = pk2(h0, h1); l.x = pk2(l0, l1);
    split_bf16(a.z, h0, l0); split_bf16(a.w, h1, l1);
    h.y = pk2(h0, h1); l.y = pk2(l0, l1);
    split_bf16(b.x, h0, l0); split_bf16(b.y, h1, l1);
    h.z = pk2(h0, h1); l.z = pk2(l0, l1);
    split_bf16(b.z, h0, l0); split_bf16(b.w, h1, l1);
    h.w = pk2(h0, h1); l.w = pk2(l0, l1);
}

__device__ __forceinline__ void cp16(uint32_t s, const void* g) {
    asm volatile("cp.async.cg.shared.global [%0], [%1], 16;" :: "r"(s), "l"(g));
}

// ---------------- top-K: smem-resident keys, radix select + bitonic sort ----
extern __shared__ unsigned skeys[];   // NN unsigned = 128 KB dynamic smem

__global__ void __launch_bounds__(1024) topk_kernel(const float* __restrict__ scores) {
    const int b = blockIdx.x;
    const float* s = scores + (size_t)b * NN;
    const int tid = threadIdx.x;

    __shared__ unsigned hist[256];
    __shared__ unsigned sh_prefix, sh_mask, sh_remk;
    __shared__ int sh_cntgt, sh_cnteq;
    __shared__ unsigned long long sel[512];
    __shared__ int eq[1024];

    if (tid == 0) { sh_prefix = 0u; sh_mask = 0u; sh_remk = KK; }
    if (tid < 256) hist[tid] = 0u;
    __syncthreads();

    for (int i = tid; i < NN; i += 1024) {
        unsigned k = fkey(__ldg(&s[i]));
        skeys[i] = k;
        atomicAdd(&hist[k >> 24], 1u);
    }
    __syncthreads();

    for (int pass = 0; pass < 4; pass++) {
        const int shift = 24 - pass * 8;
        if (tid == 0) {
            unsigned remk = sh_remk, acc = 0u;
            int d;
            for (d = 255; d >= 0; d--) {
                if (acc + hist[d] >= remk) break;
                acc += hist[d];
            }
            sh_remk  = remk - acc;
            sh_prefix = sh_prefix | ((unsigned)d << shift);
            sh_mask   = sh_mask | (0xFFu << shift);
            sh_cntgt = 0; sh_cnteq = 0;
        }
        __syncthreads();
        if (pass == 3) break;
        if (tid < 256) hist[tid] = 0u;
        __syncthreads();
        const unsigned prefix = sh_prefix, mask = sh_mask;
        const int nshift = shift - 8;
        for (int i = tid; i < NN; i += 1024) {
            unsigned k = skeys[i];
            if ((k & mask) == prefix) atomicAdd(&hist[(k >> nshift) & 255u], 1u);
        }
        __syncthreads();
    }

    const unsigned Tkey = sh_prefix;
    const int remk = (int)sh_remk;

    for (int i = tid; i < NN; i += 1024) {
        unsigned k = skeys[i];
        if (k > Tkey) {
            int p = atomicAdd(&sh_cntgt, 1);
            sel[p] = ((unsigned long long)k << 32) | (unsigned)(0xFFFFFFFFu - (unsigned)i);
        } else if (k == Tkey) {
            int p = atomicAdd(&sh_cnteq, 1);
            if (p < 1024) eq[p] = i;
        }
    }
    __syncthreads();
    const int cntgt = sh_cntgt;
    const int cnteq = min(sh_cnteq, 1024);

    if (tid >= cnteq) eq[tid] = 0x7FFFFFFF;
    __syncthreads();
    for (unsigned k = 2; k <= 1024; k <<= 1)
        for (unsigned j = k >> 1; j > 0; j >>= 1) {
            unsigned i = tid, ixj = i ^ j;
            if (ixj > i) {
                int a = eq[i], c = eq[ixj];
                bool up = ((i & k) == 0);
                if ((a > c) == up) { eq[i] = c; eq[ixj] = a; }
            }
            __syncthreads();
        }
    for (int jj = tid; jj < remk; jj += 1024)
        sel[cntgt + jj] = ((unsigned long long)Tkey << 32) |
                          (unsigned)(0xFFFFFFFFu - (unsigned)eq[jj]);
    __syncthreads();

    for (unsigned k = 2; k <= 512; k <<= 1)
        for (unsigned j = k >> 1; j > 0; j >>= 1) {
            if (tid < 512) {
                unsigned i = tid, ixj = i ^ j;
                if (ixj > i) {
                    unsigned long long a = sel[i], c = sel[ixj];
                    bool up = ((i & k) == 0);
                    if ((a > c) == up) { sel[i] = c; sel[ixj] = a; }
                }
            }
            __syncthreads();
        }
    if (tid < 512)
        g_idx[b * KK + tid] =
            (int)(0xFFFFFFFFu - (unsigned)(sel[511 - tid] & 0xFFFFFFFFull));
}

// -------- weight split: proj_w and kv weights in ONE launch ---------------
__global__ void __launch_bounds__(128)
conv_w_all(const float* __restrict__ Wp, const float* __restrict__ Wkv) {
    const int r = blockIdx.x;   // 0..EE+2EE-1
    if (r < EE) {
        for (int c = threadIdx.x; c < DD; c += 128) {
            bf16 h, l;
            split_bf16(Wp[(size_t)r * DD + c], h, l);
            g_wph[(size_t)r * DD + c] = h;
            g_wpl[(size_t)r * DD + c] = l;
        }
    } else {
        const int rr = r - EE;
        for (int c = threadIdx.x; c < EE; c += 128) {
            bf16 h, l;
            split_bf16(Wkv[(size_t)rr * EE + c], h, l);
            g_wkh[(size_t)rr * EE + c] = h;
            g_wkl[(size_t)rr * EE + c] = l;
        }
    }
}

// ============== tensor-core split-bf16 GEMM: C = A @ W^T + bias ============
// A fp32 [rows, Kd] (optionally gathered via idxp from gfeat); split to bf16
// hi/lo in the loader. W pre-split bf16. CTA tile 128x128, warp tile 32x64,
// mma m16n8k16 x 3 products (hh, hl, lh), W staged via cp.async.
#define AP 40          // smem pitch in bf16 (80B: conflict-free ldmatrix)
#define SA_ELEM (128 * AP)
#define SW_ELEM (128 * AP)
#define TC_SMEM ((2 * SA_ELEM + 2 * SW_ELEM) * 2 * 2)  // 81920 bytes

__device__ __forceinline__ void ldsm4(uint32_t r[4], uint32_t addr) {
    asm volatile("ldmatrix.sync.aligned.m8n8.x4.shared.b16 {%0,%1,%2,%3}, [%4];"
                 : "=r"(r[0]), "=r"(r[1]), "=r"(r[2]), "=r"(r[3]) : "r"(addr));
}
__device__ __forceinline__ void mma_bf16(float c[4], const uint32_t a[4],
                                         uint32_t b0, uint32_t b1) {
    asm volatile(
        "mma.sync.aligned.m16n8k16.row.col.f32.bf16.bf16.f32 "
        "{%0,%1,%2,%3}, {%4,%5,%6,%7}, {%8,%9}, {%0,%1,%2,%3};"
        : "+f"(c[0]), "+f"(c[1]), "+f"(c[2]), "+f"(c[3])
        : "r"(a[0]), "r"(a[1]), "r"(a[2]), "r"(a[3]), "r"(b0), "r"(b1));
}

#define LOAD_A(K0)                                                        \
    {                                                                     \
        float4 x0 = *(const float4*)(gA0 + (K0));                         \
        float4 x1 = *(const float4*)(gA0 + (K0) + 4);                     \
        float4 y0 = *(const float4*)(gA1 + (K0));                         \
        float4 y1 = *(const float4*)(gA1 + (K0) + 4);                     \
        pack8(x0, x1, pAh0, pAl0);                                        \
        pack8(y0, y1, pAh1, pAl1);                                        \
    }

#define LOAD_W(BUF, K0)                                                   \
    {                                                                     \
        cp16(baseWh + 2u * ((BUF) * SW_ELEM + arow * AP + achk), gWh0 + (K0)); \
        cp16(baseWh + 2u * ((BUF) * SW_ELEM + (arow + 64) * AP + achk), gWh1 + (K0)); \
        cp16(baseWl + 2u * ((BUF) * SW_ELEM + arow * AP + achk), gWl0 + (K0)); \
        cp16(baseWl + 2u * ((BUF) * SW_ELEM + (arow + 64) * AP + achk), gWl1 + (K0)); \
        asm volatile("cp.async.commit_group;\n" ::: "memory");            \
    }

#define STS_A(BUF)                                                        \
    {                                                                     \
        *(uint4*)&sAh[(BUF) * SA_ELEM + arow * AP + achk]        = pAh0;  \
        *(uint4*)&sAh[(BUF) * SA_ELEM + (arow + 64) * AP + achk] = pAh1;  \
        *(uint4*)&sAl[(BUF) * SA_ELEM + arow * AP + achk]        = pAl0;  \
        *(uint4*)&sAl[(BUF) * SA_ELEM + (arow + 64) * AP + achk] = pAl1;  \
    }

#define TC_COMPUTE(BUF)                                                   \
    _Pragma("unroll")                                                     \
    for (int ks = 0; ks < 32; ks += 16) {                                 \
        uint32_t ah[2][4], al[2][4];                                      \
        _Pragma("unroll")                                                 \
        for (int mt = 0; mt < 2; mt++) {                                  \
            uint32_t off = 2u * ((BUF) * SA_ELEM + (wm + mt * 16) * AP + aoffA + ks); \
            ldsm4(ah[mt], baseAh + off);                                  \
            ldsm4(al[mt], baseAl + off);                                  \
        }                                                                 \
        _Pragma("unroll")                                                 \
        for (int hf = 0; hf < 2; hf++) {                                  \
            uint32_t wh[2][4], wl[2][4];                                  \
            _Pragma("unroll")                                             \
            for (int np = 0; np < 2; np++) {                              \
                uint32_t off = 2u * ((BUF) * SW_ELEM + (wn + (hf * 2 + np) * 16) * AP + woffW + ks); \
                ldsm4(wh[np], baseWh + off);                              \
                ldsm4(wl[np], baseWl + off);                              \
            }                                                             \
            _Pragma("unroll")                                             \
            for (int mt = 0; mt < 2; mt++)                                \
                _Pragma("unroll")                                         \
                for (int nt = 0; nt < 4; nt++) {                          \
                    uint32_t bh0 = wh[nt >> 1][(nt & 1) * 2];             \
                    uint32_t bh1 = wh[nt >> 1][(nt & 1) * 2 + 1];         \
                    uint32_t bl0 = wl[nt >> 1][(nt & 1) * 2];             \
                    uint32_t bl1 = wl[nt >> 1][(nt & 1) * 2 + 1];         \
                    mma_bf16(acc[mt][hf * 4 + nt], ah[mt], bh0, bh1);     \
                    mma_bf16(acc[mt][hf * 4 + nt], ah[mt], bl0, bl1);     \
                    mma_bf16(acc[mt][hf * 4 + nt], al[mt], bh0, bh1);     \
                }                                                         \
        }                                                                 \
    }

__global__ void __launch_bounds__(256, 2)
gemm_tc(const float* __restrict__ A, long long strideA,
        const bf16* __restrict__ Wh, const bf16* __restrict__ Wl,
        const float* __restrict__ bias,
        float* __restrict__ C, long long strideC,
        int Kd,
        const int* __restrict__ idxp, const float* __restrict__ gfeat) {
    extern __shared__ __align__(16) char smraw[];
    bf16* sAh = (bf16*)smraw;
    bf16* sAl = sAh + 2 * SA_ELEM;
    bf16* sWh = sAl + 2 * SA_ELEM;
    bf16* sWl = sWh + 2 * SW_ELEM;

    const int b = blockIdx.z;
    const int row0 = blockIdx.y * 128, col0 = blockIdx.x * 128;
    const int N = gridDim.x * 128;
    const int tid = threadIdx.x;
    const int lane = tid & 31, wid = tid >> 5;
    const int wm = (wid & 3) * 32, wn = (wid >> 2) * 64;

    const uint32_t baseAh = (uint32_t)__cvta_generic_to_shared(sAh);
    const uint32_t baseAl = (uint32_t)__cvta_generic_to_shared(sAl);
    const uint32_t baseWh = (uint32_t)__cvta_generic_to_shared(sWh);
    const uint32_t baseWl = (uint32_t)__cvta_generic_to_shared(sWl);
    const uint32_t aoffA = (lane & 15) * AP + ((lane >> 4) << 3);
    const uint32_t woffW = ((lane & 7) + ((lane & 16) >> 1)) * AP + (lane & 8);

    // loaders: 128 rows x 32-col chunk; thread -> rows (arow, arow+64), 8 cols
    const int arow = tid >> 2;           // 0..63
    const int achk = (tid & 3) * 8;
    const float* gA0;
    const float* gA1;
    if (idxp) {
        const int* ib = idxp + b * KK;
        gA0 = gfeat + ((size_t)b * NN + ib[row0 + arow]) * Kd + achk;
        gA1 = gfeat + ((size_t)b * NN + ib[row0 + arow + 64]) * Kd + achk;
    } else {
        const float* Ab = A + (long long)b * strideA;
        gA0 = Ab + (size_t)(row0 + arow) * Kd + achk;
        gA1 = Ab + (size_t)(row0 + arow + 64) * Kd + achk;
    }
    const bf16* gWh0 = Wh + (size_t)(col0 + arow) * Kd + achk;
    const bf16* gWh1 = Wh + (size_t)(col0 + arow + 64) * Kd + achk;
    const bf16* gWl0 = Wl + (size_t)(col0 + arow) * Kd + achk;
    const bf16* gWl1 = Wl + (size_t)(col0 + arow + 64) * Kd + achk;

    float acc[2][8][4];
#pragma unroll
    for (int mt = 0; mt < 2; mt++)
#pragma unroll
        for (int nt = 0; nt < 8; nt++)
#pragma unroll
            for (int i = 0; i < 4; i++) acc[mt][nt][i] = 0.f;

    uint4 pAh0, pAh1, pAl0, pAl1;
    LOAD_A(0)
    LOAD_W(0, 0)
    STS_A(0)
    asm volatile("cp.async.wait_group 0;\n" ::: "memory");
    __syncthreads();

    int buf = 0;
    for (int k0 = 32; k0 < Kd; k0 += 32) {
        LOAD_A(k0)
        LOAD_W(buf ^ 1, k0)
        TC_COMPUTE(buf)
        STS_A(buf ^ 1)
        asm volatile("cp.async.wait_group 0;\n" ::: "memory");
        __syncthreads();
        buf ^= 1;
    }
    TC_COMPUTE(buf)

    // epilogue: bias + fp32 store
    const int g = lane >> 2, tq = (lane & 3) * 2;
#pragma unroll
    for (int mt = 0; mt < 2; mt++)
#pragma unroll
        for (int nt = 0; nt < 8; nt++) {
            int r = row0 + wm + mt * 16 + g;
            int cc = col0 + wn + nt * 8 + tq;
            float b0 = bias[cc], b1 = bias[cc + 1];
            size_t i0 = (size_t)((long long)b * strideC) + (size_t)r * N + cc;
            size_t i1 = (size_t)((long long)b * strideC) + (size_t)(r + 8) * N + cc;
            *(float2*)(C + i0) = make_float2(acc[mt][nt][0] + b0, acc[mt][nt][1] + b1);
            *(float2*)(C + i1) = make_float2(acc[mt][nt][2] + b0, acc[mt][nt][3] + b1);
        }
}

// ============ split-K GEMM partials: part[kc] = A @ W^T (chunk kc) =========
// qmode: A row m -> ((m>>4)*KK + (m&15))  (first 16 rows of each batch of g_x)
#define SKP 68

#define SK_STS(BUF)                                                       \
    {                                                                     \
        float* as = As[BUF]; float* bs = Bs[BUF];                         \
        as[(lc + 0) * SKP + lr] = av.x;                                   \
        as[(lc + 1) * SKP + lr] = av.y;                                   \
        as[(lc + 2) * SKP + lr] = av.z;                                   \
        as[(lc + 3) * SKP + lr] = av.w;                                   \
        bs[(lc + 0) * SKP + lr] = bv.x;                                   \
        bs[(lc + 1) * SKP + lr] = bv.y;                                   \
        bs[(lc + 2) * SKP + lr] = bv.z;                                   \
        bs[(lc + 3) * SKP + lr] = bv.w;                                   \
    }

#define SK_COMPUTE(BUF)                                                   \
    _Pragma("unroll")                                                     \
    for (int k = 0; k < 16; k++) {                                        \
        float a[4], bb[4];                                                \
        *(float4*)a  = *(const float4*)&As[BUF][k * SKP + ty4];           \
        *(float4*)bb = *(const float4*)&Bs[BUF][k * SKP + tx4];           \
        _Pragma("unroll")                                                 \
        for (int i = 0; i < 4; i++)                                       \
            _Pragma("unroll")                                             \
            for (int j = 0; j < 4; j++)                                   \
                acc[i][j] = fmaf(a[i], bb[j], acc[i][j]);                 \
    }

__global__ void __launch_bounds__(256)
gemm_splitk(const float* __restrict__ A, const float* __restrict__ W,
            float* __restrict__ part, int qmode) {
    const int kc = blockIdx.z;
    const int row0 = blockIdx.y * 64, col0 = blockIdx.x * 64;
    const int tid = threadIdx.x;
    const int tx4 = (tid & 15) * 4, ty4 = (tid >> 4) * 4;
    const int lr = tid >> 2, lc = (tid & 3) << 2;

    __shared__ __align__(16) float As[2][16 * SKP];
    __shared__ __align__(16) float Bs[2][16 * SKP];

    long long arow = row0 + lr;
    if (qmode) arow = (arow >> 4) * KK + (arow & 15);
    const float* Ar = A + (size_t)arow * EE + kc * 128 + lc;
    const float* Wr = W + (size_t)(col0 + lr) * EE + kc * 128 + lc;

    float acc[4][4];
#pragma unroll
    for (int i = 0; i < 4; i++)
#pragma unroll
        for (int j = 0; j < 4; j++) acc[i][j] = 0.f;

    float4 av = *(const float4*)(Ar);
    float4 bv = *(const float4*)(Wr);
    SK_STS(0)
    __syncthreads();

    int buf = 0;
#pragma unroll
    for (int k0 = 16; k0 < 128; k0 += 16) {
        av = *(const float4*)(Ar + k0);
        bv = *(const float4*)(Wr + k0);
        SK_COMPUTE(buf)
        SK_STS(buf ^ 1)
        __syncthreads();
        buf ^= 1;
    }
    SK_COMPUTE(buf)

    float* pp = part + (size_t)kc * (BB * TT * EE);
#pragma unroll
    for (int i = 0; i < 4; i++) {
        float4 v;
        v.x = acc[i][0]; v.y = acc[i][1]; v.z = acc[i][2]; v.w = acc[i][3];
        *(float4*)(pp + (size_t)(row0 + ty4 + i) * EE + col0 + tx4) = v;
    }
}

// -------- epi_q: g_q = (sum(part) + bq) / 8 -------------------------------
__global__ void __launch_bounds__(128)
epi_q(const float* __restrict__ bq) {
    const int row = blockIdx.x;
    const int tid = threadIdx.x;
#pragma unroll
    for (int u = 0; u < 4; u++) {
        int e = tid + u * 128;
        size_t o = (size_t)row * EE + e;
        float t = g_part[o] + g_part[o + 1 * BB * TT * EE] +
                  g_part[o + 2 * BB * TT * EE] + g_part[o + 3 * BB * TT * EE];
        g_q[o] = (t + bq[e]) * 0.125f;
    }
}

// -------- attention chunk: partial softmax numerator over 128 keys ---------
__global__ void __launch_bounds__(256)
attn_chunk() {
    const int h = blockIdx.x, b = blockIdx.y, c = blockIdx.z;
    const float* kb = g_kv + (size_t)b * KK * 2 * EE + h * 64;
    const float* vb = kb + EE;

    __shared__ float qs[TT][64];
    __shared__ float ks[CK * 65];
    __shared__ float lg[TT][CK];
    __shared__ float vs[32][68];
    const int tid = threadIdx.x;

    {
        int t = tid >> 4;
        int d = (tid * 4) & 63;
        *(float4*)&qs[t][d] =
            *(const float4*)(g_q + ((size_t)b * TT + t) * EE + h * 64 + d);
    }
    const int vr = tid >> 4, vc = (tid & 15) * 4;
    for (int r0 = 0; r0 < CK; r0 += 16) {
        float4 k4 = *(const float4*)(kb + (size_t)(c * CK + r0 + vr) * (2 * EE) + vc);
        float* kp = &ks[(r0 + vr) * 65 + vc];
        kp[0] = k4.x; kp[1] = k4.y; kp[2] = k4.z; kp[3] = k4.w;
    }
    __syncthreads();

    {
        const int kk = tid & 127, th = tid >> 7;
        float acc[8];
#pragma unroll
        for (int i = 0; i < 8; i++) acc[i] = 0.f;
        const float* kr = &ks[kk * 65];
#pragma unroll 8
        for (int d = 0; d < 64; d++) {
            float kv = kr[d];
#pragma unroll
            for (int i = 0; i < 8; i++)
                acc[i] = fmaf(qs[th * 8 + i][d], kv, acc[i]);
        }
#pragma unroll
        for (int i = 0; i < 8; i++) lg[th * 8 + i][kk] = acc[i];
    }
    __syncthreads();

    const int w = tid >> 5, lane = tid & 31;
    for (int t = w; t < TT; t += 8) {
        float m = -1e30f;
        for (int i = lane; i < CK; i += 32) m = fmaxf(m, lg[t][i]);
#pragma unroll
        for (int o = 16; o > 0; o >>= 1) m = fmaxf(m, __shfl_xor_sync(0xFFFFFFFFu, m, o));
        float ssum = 0.f;
        for (int i = lane; i < CK; i += 32) {
            float e = __expf(lg[t][i] - m);
            lg[t][i] = e; ssum += e;
        }
#pragma unroll
        for (int o = 16; o > 0; o >>= 1) ssum += __shfl_xor_sync(0xFFFFFFFFu, ssum, o);
        if (lane == 0) {
            g_m[((size_t)(c * BB + b) * HH + h) * TT + t] = m;
            g_l[((size_t)(c * BB + b) * HH + h) * TT + t] = ssum;
        }
    }

    const int d = tid & 63, tg = tid >> 6;
    float acc4[4] = {0.f, 0.f, 0.f, 0.f};
    for (int kk0 = 0; kk0 < CK; kk0 += 32) {
        __syncthreads();
        const float* vrow = vb + (size_t)(c * CK + kk0 + vr) * (2 * EE) + vc;
        float4 v0 = *(const float4*)(vrow);
        float4 v1 = *(const float4*)(vrow + (size_t)16 * 2 * EE);
        *(float4*)&vs[vr][vc]      = v0;
        *(float4*)&vs[vr + 16][vc] = v1;
        __syncthreads();
#pragma unroll
        for (int r = 0; r < 32; r++) {
            float v = vs[r][d];
#pragma unroll
            for (int i = 0; i < 4; i++)
                acc4[i] = fmaf(lg[tg + i * 4][kk0 + r], v, acc4[i]);
        }
    }
#pragma unroll
    for (int i = 0; i < 4; i++)
        g_part[((size_t)(c * BB + b) * TT + tg + i * 4) * EE + h * 64 + d] = acc4[i];
}

// -------- attention combine: merge 4 chunks -> g_o ------------------------
__global__ void __launch_bounds__(256)
attn_combine() {
    const int h = blockIdx.x, b = blockIdx.y;
    const int tid = threadIdx.x;
    const int d = tid & 63, tg = tid >> 6;
#pragma unroll
    for (int i = 0; i < 4; i++) {
        const int t = tg + i * 4;
        float m[NC], l[NC];
#pragma unroll
        for (int c = 0; c < NC; c++) {
            m[c] = g_m[((size_t)(c * BB + b) * HH + h) * TT + t];
            l[c] = g_l[((size_t)(c * BB + b) * HH + h) * TT + t];
        }
        float mstar = fmaxf(fmaxf(m[0], m[1]), fmaxf(m[2], m[3]));
        float wgt[NC], denom = 0.f;
#pragma unroll
        for (int c = 0; c < NC; c++) {
            wgt[c] = __expf(m[c] - mstar);
            denom += wgt[c] * l[c];
        }
        float o = 0.f;
#pragma unroll
        for (int c = 0; c < NC; c++)
            o += wgt[c] *
                 g_part[((size_t)(c * BB + b) * TT + t) * EE + h * 64 + d];
        g_o[((size_t)b * TT + t) * EE + h * 64 + d] = o / denom;
    }
}

// -------- epilogue 1: y = sum(part) + bo + x_res ; z = LN(y) --------------
__global__ void __launch_bounds__(128)
epi_ln(const float* __restrict__ bo,
       const float* __restrict__ lng, const float* __restrict__ lnb) {
    const int row = blockIdx.x;
    const int tid = threadIdx.x;
    const float* xres = g_x + ((size_t)(row >> 4) * KK + (row & 15)) * EE;
    float* zr = g_z + (size_t)row * EE;
    __shared__ float red[4];

    float v[4];
#pragma unroll
    for (int u = 0; u < 4; u++) {
        int e = tid + u * 128;
        size_t o = (size_t)row * EE + e;
        float s = g_part[o] + g_part[o + 1 * BB * TT * EE] +
                  g_part[o + 2 * BB * TT * EE] + g_part[o + 3 * BB * TT * EE];
        v[u] = s + bo[e] + xres[e];
    }

    float s = v[0] + v[1] + v[2] + v[3];
#pragma unroll
    for (int o = 16; o > 0; o >>= 1) s += __shfl_xor_sync(0xFFFFFFFFu, s, o);
    if ((tid & 31) == 0) red[tid >> 5] = s;
    __syncthreads();
    const float mu = (red[0] + red[1] + red[2] + red[3]) / EE;
    __syncthreads();

    float q = 0.f;
#pragma unroll
    for (int u = 0; u < 4; u++) { float dlt = v[u] - mu; q += dlt * dlt; }
#pragma unroll
    for (int o = 16; o > 0; o >>= 1) q += __shfl_xor_sync(0xFFFFFFFFu, q, o);
    if ((tid & 31) == 0) red[tid >> 5] = q;
    __syncthreads();
    const float rstd = rsqrtf((red[0] + red[1] + red[2] + red[3]) / EE + 1e-5f);

#pragma unroll
    for (int u = 0; u < 4; u++) {
        int e = tid + u * 128;
        zr[e] = (v[u] - mu) * rstd * lng[e] + lnb[e];
    }
}

// -------- epilogue 2: out = z + gelu(sum(part) + bf) ----------------------
__global__ void __launch_bounds__(128)
epi_ffn(const float* __restrict__ bf, float* __restrict__ out) {
    const int row = blockIdx.x;
    const int tid = threadIdx.x;
    const float* zr = g_z + (size_t)row * EE;
    float* outp = out + (size_t)row * EE;
#pragma unroll
    for (int u = 0; u < 4; u++) {
        int e = tid + u * 128;
        size_t o = (size_t)row * EE + e;
        float t = g_part[o] + g_part[o + 1 * BB * TT * EE] +
                  g_part[o + 2 * BB * TT * EE] + g_part[o + 3 * BB * TT * EE] +
                  bf[e];
        float g = 0.5f * t * (1.f + erff(t * 0.70710678118654752f));
        outp[e] = zr[e] + g;
    }
}

// ---------------- launch ----------------
extern "C" void kernel_launch(void* const* d_in, const int* in_sizes, int n_in,
                              void* d_out, int out_size) {
    (void)in_sizes; (void)n_in; (void)out_size;
    const float* feats  = (const float*)d_in[0];
    const float* scores = (const float*)d_in[1];
    const float* proj_w = (const float*)d_in[2];
    const float* proj_b = (const float*)d_in[3];
    const float* in_w   = (const float*)d_in[4];
    const float* in_b   = (const float*)d_in[5];
    const float* out_w  = (const float*)d_in[6];
    const float* out_b  = (const float*)d_in[7];
    const float* ln_g   = (const float*)d_in[8];
    const float* ln_b   = (const float*)d_in[9];
    const float* ffn_w  = (const float*)d_in[10];
    const float* ffn_b  = (const float*)d_in[11];
    float* out = (float*)d_out;

    float *px, *pkv, *po, *pz, *ppart;
    bf16 *pwph, *pwpl, *pwkh, *pwkl;
    int* pidx;
    cudaGetSymbolAddress((void**)&px,    g_x);
    cudaGetSymbolAddress((void**)&pkv,   g_kv);
    cudaGetSymbolAddress((void**)&po,    g_o);
    cudaGetSymbolAddress((void**)&pz,    g_z);
    cudaGetSymbolAddress((void**)&ppart, g_part);
    cudaGetSymbolAddress((void**)&pidx,  g_idx);
    cudaGetSymbolAddress((void**)&pwph,  g_wph);
    cudaGetSymbolAddress((void**)&pwpl,  g_wpl);
    cudaGetSymbolAddress((void**)&pwkh,  g_wkh);
    cudaGetSymbolAddress((void**)&pwkl,  g_wkl);

    static int smem_set = 0;
    if (!smem_set) {
        cudaFuncSetAttribute(topk_kernel,
                             cudaFuncAttributeMaxDynamicSharedMemorySize,
                             NN * (int)sizeof(unsigned));
        cudaFuncSetAttribute(gemm_tc,
                             cudaFuncAttributeMaxDynamicSharedMemorySize,
                             TC_SMEM);
        smem_set = 1;
    }

    // 1: weight split (independent of topk)
    conv_w_all<<<3 * EE, 128>>>(proj_w, in_w + EE * EE);
    // 2: top-k
    topk_kernel<<<BB, 1024, NN * sizeof(unsigned)>>>(scores);
    // 3: x = feats[idx] @ proj_w^T + proj_b  (gather + split fused in loader)
    gemm_tc<<<dim3(EE / 128, KK / 128, BB), 256, TC_SMEM>>>(
        nullptr, 0LL, pwph, pwpl, proj_b, px, (long long)KK * EE, DD,
        pidx, feats);
    // 4: kv = x @ [Wk;Wv]^T + b   <-- profiled launch
    gemm_tc<<<dim3(2 * EE / 128, KK / 128, BB), 256, TC_SMEM>>>(
        px, (long long)KK * EE, pwkh, pwkl, in_b + EE, pkv,
        (long long)KK * 2 * EE, EE, nullptr, nullptr);

    // q = (x[:, :16] @ Wq^T + bq)/8  via split-K + epilogue
    gemm_splitk<<<dim3(EE / 64, (BB * TT) / 64, 4), 256>>>(px, in_w, ppart, 1);
    epi_q<<<BB * TT, 128>>>(in_b);

    // attention: chunked flash partials, combine
    attn_chunk<<<dim3(HH, BB, NC), 256>>>();
    attn_combine<<<dim3(HH, BB), 256>>>();

    // out_proj split-K partials, then fused (sum + bias + residual + LN)
    gemm_splitk<<<dim3(EE / 64, (BB * TT) / 64, 4), 256>>>(po, out_w, ppart, 0);
    epi_ln<<<BB * TT, 128>>>(out_b, ln_g, ln_b);

    // FFN split-K partials, then fused (sum + bias + GELU + residual)
    gemm_splitk<<<dim3(EE / 64, (BB * TT) / 64, 4), 256>>>(pz, ffn_w, ppart, 0);
    epi_ffn<<<BB * TT, 128>>>(ffn_b, out);
}